// round 3
// baseline (speedup 1.0000x reference)
#include <cuda_runtime.h>
#include <math.h>

#define DM   2048
#define NH   16
#define DH   128
#define SEQ  2048
#define BATCH 4
#define M_TOTAL (BATCH * SEQ)   // 8192
#define BHEADS  (BATCH * NH)    // 64
#define HALF    (DH / 2)        // 64

// Scratch (allocations are forbidden; __device__ globals are the sanctioned path)
__device__ float g_Q[BHEADS * SEQ * DH];   // [b,h,s,d]
__device__ float g_K[BHEADS * SEQ * DH];
__device__ float g_V[BHEADS * SEQ * DH];
__device__ float g_Y[M_TOTAL * DM];        // [b,s,h*d]

// ---------------------------------------------------------------------------
// NT SGEMM: C[M,N] = A[M,K] * W[N,K]^T   (M=8192, N=K=2048)
// mode 0: scatter C to [b, head, s, d] layout (for Q/K/V)
// mode 1: plain row-major [M, N] (final projection)
// 128x128 block tile, 256 threads, 8x8 per-thread microtile, K-step 8.
// ---------------------------------------------------------------------------
__global__ __launch_bounds__(256, 2)
void gemm_nt_kernel(const float* __restrict__ A, const float* __restrict__ W,
                    float* __restrict__ out, int mode)
{
    __shared__ __align__(16) float As[8][132];
    __shared__ __align__(16) float Bs[8][132];

    const int bm  = blockIdx.y * 128;
    const int bn  = blockIdx.x * 128;
    const int tid = threadIdx.x;
    const int tm  = tid >> 4;          // 0..15
    const int tn  = tid & 15;          // 0..15
    const int lrow = tid >> 1;         // 0..127 (tile row for loads)
    const int lk4  = (tid & 1) * 4;    // 0 or 4

    float acc[8][8];
#pragma unroll
    for (int i = 0; i < 8; i++)
#pragma unroll
        for (int j = 0; j < 8; j++) acc[i][j] = 0.0f;

    const float* Arow = A + (size_t)(bm + lrow) * DM;
    const float* Wrow = W + (size_t)(bn + lrow) * DM;

    for (int kt = 0; kt < DM; kt += 8) {
        float4 av = *(const float4*)(Arow + kt + lk4);
        float4 bv = *(const float4*)(Wrow + kt + lk4);
        __syncthreads();
        As[lk4 + 0][lrow] = av.x; As[lk4 + 1][lrow] = av.y;
        As[lk4 + 2][lrow] = av.z; As[lk4 + 3][lrow] = av.w;
        Bs[lk4 + 0][lrow] = bv.x; Bs[lk4 + 1][lrow] = bv.y;
        Bs[lk4 + 2][lrow] = bv.z; Bs[lk4 + 3][lrow] = bv.w;
        __syncthreads();
#pragma unroll
        for (int kk = 0; kk < 8; kk++) {
            float4 a0 = *(const float4*)&As[kk][tm * 4];
            float4 a1 = *(const float4*)&As[kk][tm * 4 + 64];
            float4 b0 = *(const float4*)&Bs[kk][tn * 4];
            float4 b1 = *(const float4*)&Bs[kk][tn * 4 + 64];
            float ar[8] = {a0.x, a0.y, a0.z, a0.w, a1.x, a1.y, a1.z, a1.w};
            float br[8] = {b0.x, b0.y, b0.z, b0.w, b1.x, b1.y, b1.z, b1.w};
#pragma unroll
            for (int i = 0; i < 8; i++)
#pragma unroll
                for (int j = 0; j < 8; j++)
                    acc[i][j] += ar[i] * br[j];
        }
    }

#pragma unroll
    for (int i = 0; i < 8; i++) {
        int row = bm + tm * 4 + (i & 3) + ((i >> 2) << 6);
#pragma unroll
        for (int jh = 0; jh < 2; jh++) {
            int col = bn + tn * 4 + (jh << 6);
            float4 v = make_float4(acc[i][jh * 4 + 0], acc[i][jh * 4 + 1],
                                   acc[i][jh * 4 + 2], acc[i][jh * 4 + 3]);
            if (mode == 0) {
                int bi = row >> 11, si = row & (SEQ - 1);
                int head = col >> 7, dd = col & (DH - 1);
                float* dst = out + ((((size_t)bi * NH + head) * SEQ + si) * DH + dd);
                *(float4*)dst = v;
            } else {
                *(float4*)(out + (size_t)row * DM + col) = v;
            }
        }
    }
}

// ---------------------------------------------------------------------------
// RoPE applied in place to g_Q and g_K. Handles token_positions being either
// int32 (JAX default, x64 disabled) or true int64: detected from the data
// (arange: reinterpreted-int32 word 1 is 1 for int32, 0 for int64).
// ---------------------------------------------------------------------------
__global__ void rope_kernel(const int* __restrict__ pos_raw)
{
    const int idx   = blockIdx.x * blockDim.x + threadIdx.x;
    const int per   = BHEADS * SEQ * HALF;       // pairs per tensor
    if (idx >= 2 * per) return;
    const int which = (idx >= per) ? 1 : 0;
    const int r     = idx - which * per;
    const int p     = r & (HALF - 1);
    const int s     = (r >> 6) & (SEQ - 1);
    const int bh    = r >> 17;                   // r / (SEQ*HALF)

    const bool is64 = (pos_raw[1] == 0);
    const int posv_i = is64 ? pos_raw[2 * s] : pos_raw[s];
    const float posv = (float)posv_i;

    // theta^(-p/half) = exp2(-p * log2(theta)/half), log2(10000)=13.2877123795...
    const float inv_freq = exp2f(-(float)p * (13.287712379549449f / 64.0f));
    const float ang = posv * inv_freq;
    float sn, cs;
    sincosf(ang, &sn, &cs);

    float* arr = which ? g_K : g_Q;
    const size_t base = ((size_t)bh * SEQ + s) * DH + 2 * p;
    const float e = arr[base], o = arr[base + 1];
    arr[base]     = e * cs - o * sn;
    arr[base + 1] = o * cs + e * sn;
}

// ---------------------------------------------------------------------------
// Causal flash attention, fp32. Br=Bc=64, d=128, 256 threads.
// Thread (tr,tc)=(tid/16,tid%16): S microtile 4 rows x 4 cols,
// O microtile 4 rows x 8 cols. Online softmax with 16-lane shfl reductions.
// ---------------------------------------------------------------------------
#define QS_STRIDE 132
#define PS_STRIDE 68
#define FLASH_SMEM_FLOATS (3 * 64 * QS_STRIDE + 64 * PS_STRIDE)

__global__ __launch_bounds__(256)
void flash_kernel(const float* __restrict__ Q, const float* __restrict__ K,
                  const float* __restrict__ V, float* __restrict__ Y)
{
    extern __shared__ float sm[];
    float* Qs = sm;
    float* Ks = Qs + 64 * QS_STRIDE;
    float* Vs = Ks + 64 * QS_STRIDE;
    float* Ps = Vs + 64 * QS_STRIDE;

    const int qb = blockIdx.x;       // query block 0..31
    const int bh = blockIdx.y;       // 0..63
    const int b  = bh >> 4, h = bh & 15;
    const int tid = threadIdx.x;
    const int tr = tid >> 4, tc = tid & 15;

    const float* Qb = Q + (size_t)bh * SEQ * DH;
    const float* Kb = K + (size_t)bh * SEQ * DH;
    const float* Vb = V + (size_t)bh * SEQ * DH;

    // load Q tile (64 x 128)
    for (int i = tid; i < 64 * 32; i += 256) {
        int rr = i >> 5, c4 = (i & 31) * 4;
        *(float4*)&Qs[rr * QS_STRIDE + c4] =
            *(const float4*)&Qb[(size_t)(qb * 64 + rr) * DH + c4];
    }

    float m_i[4], l_i[4], o[4][8];
#pragma unroll
    for (int i = 0; i < 4; i++) {
        m_i[i] = -1e30f; l_i[i] = 0.0f;
#pragma unroll
        for (int c = 0; c < 8; c++) o[i][c] = 0.0f;
    }
    const float scale = 0.08838834764831845f;  // 1/sqrt(128)

    for (int jb = 0; jb <= qb; jb++) {
        __syncthreads();  // previous iteration's consumers done
        for (int i = tid; i < 64 * 32; i += 256) {
            int rr = i >> 5, c4 = (i & 31) * 4;
            *(float4*)&Ks[rr * QS_STRIDE + c4] =
                *(const float4*)&Kb[(size_t)(jb * 64 + rr) * DH + c4];
            *(float4*)&Vs[rr * QS_STRIDE + c4] =
                *(const float4*)&Vb[(size_t)(jb * 64 + rr) * DH + c4];
        }
        __syncthreads();

        // S = Q K^T (4x4 microtile)
        float s4[4][4];
#pragma unroll
        for (int i = 0; i < 4; i++)
#pragma unroll
            for (int j = 0; j < 4; j++) s4[i][j] = 0.0f;

        for (int k = 0; k < DH; k += 4) {
            float4 q[4];
#pragma unroll
            for (int i = 0; i < 4; i++)
                q[i] = *(const float4*)&Qs[(tr * 4 + i) * QS_STRIDE + k];
#pragma unroll
            for (int j = 0; j < 4; j++) {
                float4 kv = *(const float4*)&Ks[(tc * 4 + j) * QS_STRIDE + k];
#pragma unroll
                for (int i = 0; i < 4; i++)
                    s4[i][j] += q[i].x * kv.x + q[i].y * kv.y +
                                q[i].z * kv.z + q[i].w * kv.w;
            }
        }

        const bool diag = (jb == qb);
#pragma unroll
        for (int i = 0; i < 4; i++)
#pragma unroll
            for (int j = 0; j < 4; j++) {
                s4[i][j] *= scale;
                if (diag && (tc * 4 + j) > (tr * 4 + i)) s4[i][j] = -1e30f;
            }

        // online softmax
#pragma unroll
        for (int i = 0; i < 4; i++) {
            float tmax = fmaxf(fmaxf(s4[i][0], s4[i][1]), fmaxf(s4[i][2], s4[i][3]));
#pragma unroll
            for (int off = 1; off < 16; off <<= 1)
                tmax = fmaxf(tmax, __shfl_xor_sync(0xffffffffu, tmax, off));
            float mnew = fmaxf(m_i[i], tmax);
            float alpha = __expf(m_i[i] - mnew);
            m_i[i] = mnew;
            float rs = 0.0f;
#pragma unroll
            for (int j = 0; j < 4; j++) {
                float p = __expf(s4[i][j] - mnew);
                s4[i][j] = p;
                rs += p;
            }
#pragma unroll
            for (int off = 1; off < 16; off <<= 1)
                rs += __shfl_xor_sync(0xffffffffu, rs, off);
            l_i[i] = l_i[i] * alpha + rs;
#pragma unroll
            for (int c = 0; c < 8; c++) o[i][c] *= alpha;
        }

        // stage P
#pragma unroll
        for (int i = 0; i < 4; i++)
#pragma unroll
            for (int j = 0; j < 4; j++)
                Ps[(tr * 4 + i) * PS_STRIDE + tc * 4 + j] = s4[i][j];
        __syncthreads();

        // O += P V   (4 rows x 8 cols per thread)
        for (int j = 0; j < 64; j++) {
            float p0 = Ps[(tr * 4 + 0) * PS_STRIDE + j];
            float p1 = Ps[(tr * 4 + 1) * PS_STRIDE + j];
            float p2 = Ps[(tr * 4 + 2) * PS_STRIDE + j];
            float p3 = Ps[(tr * 4 + 3) * PS_STRIDE + j];
            float4 v0 = *(const float4*)&Vs[j * QS_STRIDE + tc * 8];
            float4 v1 = *(const float4*)&Vs[j * QS_STRIDE + tc * 8 + 4];
            o[0][0] += p0 * v0.x; o[0][1] += p0 * v0.y; o[0][2] += p0 * v0.z; o[0][3] += p0 * v0.w;
            o[0][4] += p0 * v1.x; o[0][5] += p0 * v1.y; o[0][6] += p0 * v1.z; o[0][7] += p0 * v1.w;
            o[1][0] += p1 * v0.x; o[1][1] += p1 * v0.y; o[1][2] += p1 * v0.z; o[1][3] += p1 * v0.w;
            o[1][4] += p1 * v1.x; o[1][5] += p1 * v1.y; o[1][6] += p1 * v1.z; o[1][7] += p1 * v1.w;
            o[2][0] += p2 * v0.x; o[2][1] += p2 * v0.y; o[2][2] += p2 * v0.z; o[2][3] += p2 * v0.w;
            o[2][4] += p2 * v1.x; o[2][5] += p2 * v1.y; o[2][6] += p2 * v1.z; o[2][7] += p2 * v1.w;
            o[3][0] += p3 * v0.x; o[3][1] += p3 * v0.y; o[3][2] += p3 * v0.z; o[3][3] += p3 * v0.w;
            o[3][4] += p3 * v1.x; o[3][5] += p3 * v1.y; o[3][6] += p3 * v1.z; o[3][7] += p3 * v1.w;
        }
    }

    // epilogue: normalize and write into [b, s, h*d]
#pragma unroll
    for (int i = 0; i < 4; i++) {
        int q = qb * 64 + tr * 4 + i;
        float invl = 1.0f / l_i[i];
        size_t off = ((size_t)(b * SEQ + q)) * DM + h * DH + tc * 8;
        float4 w0 = make_float4(o[i][0] * invl, o[i][1] * invl, o[i][2] * invl, o[i][3] * invl);
        float4 w1 = make_float4(o[i][4] * invl, o[i][5] * invl, o[i][6] * invl, o[i][7] * invl);
        *(float4*)&Y[off]     = w0;
        *(float4*)&Y[off + 4] = w1;
    }
}

// ---------------------------------------------------------------------------
extern "C" void kernel_launch(void* const* d_in, const int* in_sizes, int n_in,
                              void* d_out, int out_size)
{
    (void)in_sizes; (void)n_in; (void)out_size;
    const float* x   = (const float*)d_in[0];
    const int*   pos = (const int*)d_in[1];   // int32 or int64: detected in-kernel
    const float* Wq  = (const float*)d_in[2];
    const float* Wk  = (const float*)d_in[3];
    const float* Wv  = (const float*)d_in[4];
    const float* Wo  = (const float*)d_in[5];
    float* out = (float*)d_out;

    float *Qp, *Kp, *Vp, *Yp;
    cudaGetSymbolAddress((void**)&Qp, g_Q);
    cudaGetSymbolAddress((void**)&Kp, g_K);
    cudaGetSymbolAddress((void**)&Vp, g_V);
    cudaGetSymbolAddress((void**)&Yp, g_Y);

    dim3 ggrid(DM / 128, M_TOTAL / 128);   // (16, 64)
    gemm_nt_kernel<<<ggrid, 256>>>(x, Wq, Qp, 0);
    gemm_nt_kernel<<<ggrid, 256>>>(x, Wk, Kp, 0);
    gemm_nt_kernel<<<ggrid, 256>>>(x, Wv, Vp, 0);

    int rope_total = 2 * BHEADS * SEQ * HALF;
    rope_kernel<<<rope_total / 256, 256>>>(pos);

    size_t smem = FLASH_SMEM_FLOATS * sizeof(float);
    cudaFuncSetAttribute(flash_kernel, cudaFuncAttributeMaxDynamicSharedMemorySize, (int)smem);
    flash_kernel<<<dim3(SEQ / 64, BHEADS), 256, smem>>>(Qp, Kp, Vp, Yp);

    gemm_nt_kernel<<<ggrid, 256>>>(Yp, Wo, out, 1);
}

// round 7
// speedup vs baseline: 1.5580x; 1.5580x over previous
#include <cuda_runtime.h>
#include <stdint.h>
#include <math.h>

#define DM   2048
#define NH   16
#define DH   128
#define SEQ  2048
#define BATCH 4
#define M_TOTAL (BATCH * SEQ)   // 8192
#define BHEADS  (BATCH * NH)    // 64
#define HALF    (DH / 2)        // 64

// Scratch (allocations forbidden; __device__ globals are the sanctioned path)
__device__ float g_Q[BHEADS * SEQ * DH];   // [b,h,s,d]
__device__ float g_K[BHEADS * SEQ * DH];
__device__ float g_V[BHEADS * SEQ * DH];
__device__ float g_Y[M_TOTAL * DM];        // [b,s,h*d]

// ---------------------------------------------------------------------------
// TF32 tensor-core NT GEMM: C[M,N] = A[M,K] * W[N,K]^T  (M=8192, N=K=2048)
// Block 128x128, BK=16, 256 threads (8 warps as 4Mx2N), warp tile 32x64,
// mma.sync.m16n8k8 tf32. Double-buffered smem, 1 barrier/iter.
// Smem layout: X[k][m'] stride 136, m' = m ^ (((k>>2)&3)<<3)  -> conflict-free
// STS and conflict-free fragment LDS; LDG is 64B/row coalesced.
// mode 0: plain row-major out; mode 1: scatter to [b,h,s,d]; mode 2: scatter+RoPE
// ---------------------------------------------------------------------------
#define BK 16
#define SA 136

__device__ __forceinline__ unsigned int f2tf32(float x) {
    unsigned int u;
    asm("cvt.rna.tf32.f32 %0, %1;" : "=r"(u) : "f"(x));
    return u;
}

__device__ __forceinline__ void mma_tf32(float4& d, const unsigned int a[4],
                                         const unsigned int b[2]) {
    asm volatile(
        "mma.sync.aligned.m16n8k8.row.col.f32.tf32.tf32.f32 "
        "{%0,%1,%2,%3}, {%4,%5,%6,%7}, {%8,%9}, {%0,%1,%2,%3};"
        : "+f"(d.x), "+f"(d.y), "+f"(d.z), "+f"(d.w)
        : "r"(a[0]), "r"(a[1]), "r"(a[2]), "r"(a[3]), "r"(b[0]), "r"(b[1]));
}

__global__ __launch_bounds__(256, 2)
void gemm_tf32_kernel(const float* __restrict__ A, const float* __restrict__ W,
                      float* __restrict__ out, int mode, const int* __restrict__ pos)
{
    __shared__ float As[2][BK * SA];
    __shared__ float Bs[2][BK * SA];

    const int tid  = threadIdx.x;
    const int lane = tid & 31;
    const int warp = tid >> 5;
    const int warpM = warp >> 1;     // 0..3
    const int warpN = warp & 1;      // 0..1
    const int bm = blockIdx.y * 128;
    const int bn = blockIdx.x * 128;

    // loader: thread covers rows (tid>>2) and (tid>>2)+64, k-chunk (tid&3)
    const int lrow = tid >> 2;       // 0..63
    const int lc   = tid & 3;        // 0..3 -> k = 4*lc + j
    const float* Aptr = A + (size_t)(bm + lrow) * DM + lc * 4;
    const float* Wptr = W + (size_t)(bn + lrow) * DM + lc * 4;
    const int sw_st  = lc << 3;      // store-side swizzle (k>>2 == lc)
    const int sbase0 = (lc * 4) * SA + (lrow ^ sw_st);
    const int sbase1 = (lc * 4) * SA + ((lrow + 64) ^ sw_st);

    float4 ra0, ra1, rb0, rb1;

    // fragment read indices
    const int fr  = (lane >> 2);     // 0..7
    const int fc  = (lane & 3);      // 0..3

    float4 acc[2][8];
#pragma unroll
    for (int mt = 0; mt < 2; mt++)
#pragma unroll
        for (int nt = 0; nt < 8; nt++) acc[mt][nt] = make_float4(0.f, 0.f, 0.f, 0.f);

    // prologue: load tile 0
    ra0 = *(const float4*)(Aptr);
    ra1 = *(const float4*)(Aptr + (size_t)64 * DM);
    rb0 = *(const float4*)(Wptr);
    rb1 = *(const float4*)(Wptr + (size_t)64 * DM);

    for (int kt = 0; kt < DM; kt += BK) {
        const int buf = (kt >> 4) & 1;
        // stage regs -> smem[buf]
        float* as = As[buf];
        float* bs = Bs[buf];
        as[sbase0 + 0 * SA] = __uint_as_float(f2tf32(ra0.x));
        as[sbase0 + 1 * SA] = __uint_as_float(f2tf32(ra0.y));
        as[sbase0 + 2 * SA] = __uint_as_float(f2tf32(ra0.z));
        as[sbase0 + 3 * SA] = __uint_as_float(f2tf32(ra0.w));
        as[sbase1 + 0 * SA] = __uint_as_float(f2tf32(ra1.x));
        as[sbase1 + 1 * SA] = __uint_as_float(f2tf32(ra1.y));
        as[sbase1 + 2 * SA] = __uint_as_float(f2tf32(ra1.z));
        as[sbase1 + 3 * SA] = __uint_as_float(f2tf32(ra1.w));
        bs[sbase0 + 0 * SA] = __uint_as_float(f2tf32(rb0.x));
        bs[sbase0 + 1 * SA] = __uint_as_float(f2tf32(rb0.y));
        bs[sbase0 + 2 * SA] = __uint_as_float(f2tf32(rb0.z));
        bs[sbase0 + 3 * SA] = __uint_as_float(f2tf32(rb0.w));
        bs[sbase1 + 0 * SA] = __uint_as_float(f2tf32(rb1.x));
        bs[sbase1 + 1 * SA] = __uint_as_float(f2tf32(rb1.y));
        bs[sbase1 + 2 * SA] = __uint_as_float(f2tf32(rb1.z));
        bs[sbase1 + 3 * SA] = __uint_as_float(f2tf32(rb1.w));
        __syncthreads();

        // issue next tile's global loads (consumed next iteration)
        if (kt + BK < DM) {
            ra0 = *(const float4*)(Aptr + kt + BK);
            ra1 = *(const float4*)(Aptr + kt + BK + (size_t)64 * DM);
            rb0 = *(const float4*)(Wptr + kt + BK);
            rb1 = *(const float4*)(Wptr + kt + BK + (size_t)64 * DM);
        }

        // compute on smem[buf]
#pragma unroll
        for (int k8 = 0; k8 < 2; k8++) {
            const int k_lo = k8 * 8 + fc;
            const int k_hi = k_lo + 4;
            const int swl = ((k_lo >> 2) & 3) << 3;
            const int swh = ((k_hi >> 2) & 3) << 3;

            unsigned int af[2][4];
#pragma unroll
            for (int mt = 0; mt < 2; mt++) {
                const int r = warpM * 32 + mt * 16 + fr;
                af[mt][0] = __float_as_uint(as[k_lo * SA + (r ^ swl)]);
                af[mt][1] = __float_as_uint(as[k_lo * SA + ((r + 8) ^ swl)]);
                af[mt][2] = __float_as_uint(as[k_hi * SA + (r ^ swh)]);
                af[mt][3] = __float_as_uint(as[k_hi * SA + ((r + 8) ^ swh)]);
            }
#pragma unroll
            for (int nt = 0; nt < 8; nt++) {
                const int n = warpN * 64 + nt * 8 + fr;
                unsigned int bf[2];
                bf[0] = __float_as_uint(bs[k_lo * SA + (n ^ swl)]);
                bf[1] = __float_as_uint(bs[k_hi * SA + (n ^ swh)]);
                mma_tf32(acc[0][nt], af[0], bf);
                mma_tf32(acc[1][nt], af[1], bf);
            }
        }
        __syncthreads();
    }

    // epilogue
    const bool is64 = (mode == 2) && (pos[1] == 0);
#pragma unroll
    for (int mt = 0; mt < 2; mt++) {
        const int gr0 = bm + warpM * 32 + mt * 16 + fr;
#pragma unroll
        for (int nt = 0; nt < 8; nt++) {
            const int gc = bn + warpN * 64 + nt * 8 + 2 * fc;
            float4 v = acc[mt][nt];
#pragma unroll
            for (int half = 0; half < 2; half++) {
                const int grow = gr0 + half * 8;
                float e = half ? v.z : v.x;
                float o = half ? v.w : v.y;
                if (mode == 0) {
                    *(float2*)(out + (size_t)grow * DM + gc) = make_float2(e, o);
                } else {
                    const int si = grow & (SEQ - 1), bi = grow >> 11;
                    const int head = gc >> 7, dd = gc & (DH - 1);
                    if (mode == 2) {
                        const int p = dd >> 1;
                        const int posv_i = is64 ? pos[2 * si] : pos[si];
                        const float inv_freq =
                            exp2f(-(float)p * (13.287712379549449f / 64.0f));
                        const float ang = (float)posv_i * inv_freq;
                        float sn, cs;
                        sincosf(ang, &sn, &cs);
                        const float e2 = e * cs - o * sn;
                        const float o2 = o * cs + e * sn;
                        e = e2; o = o2;
                    }
                    float* dst = out + ((((size_t)bi * NH + head) * SEQ + si) * DH + dd);
                    *(float2*)dst = make_float2(e, o);
                }
            }
        }
    }
}

// ---------------------------------------------------------------------------
// Causal flash attention, fp32. Br=Bc=64, d=128, 256 threads. (unchanged)
// ---------------------------------------------------------------------------
#define QS_STRIDE 132
#define PS_STRIDE 68
#define FLASH_SMEM_FLOATS (3 * 64 * QS_STRIDE + 64 * PS_STRIDE)

__global__ __launch_bounds__(256)
void flash_kernel(const float* __restrict__ Q, const float* __restrict__ K,
                  const float* __restrict__ V, float* __restrict__ Y)
{
    extern __shared__ float sm[];
    float* Qs = sm;
    float* Ks = Qs + 64 * QS_STRIDE;
    float* Vs = Ks + 64 * QS_STRIDE;
    float* Ps = Vs + 64 * QS_STRIDE;

    const int qb = blockIdx.x;
    const int bh = blockIdx.y;
    const int b  = bh >> 4, h = bh & 15;
    const int tid = threadIdx.x;
    const int tr = tid >> 4, tc = tid & 15;

    const float* Qb = Q + (size_t)bh * SEQ * DH;
    const float* Kb = K + (size_t)bh * SEQ * DH;
    const float* Vb = V + (size_t)bh * SEQ * DH;

    for (int i = tid; i < 64 * 32; i += 256) {
        int rr = i >> 5, c4 = (i & 31) * 4;
        *(float4*)&Qs[rr * QS_STRIDE + c4] =
            *(const float4*)&Qb[(size_t)(qb * 64 + rr) * DH + c4];
    }

    float m_i[4], l_i[4], o[4][8];
#pragma unroll
    for (int i = 0; i < 4; i++) {
        m_i[i] = -1e30f; l_i[i] = 0.0f;
#pragma unroll
        for (int c = 0; c < 8; c++) o[i][c] = 0.0f;
    }
    const float scale = 0.08838834764831845f;  // 1/sqrt(128)

    for (int jb = 0; jb <= qb; jb++) {
        __syncthreads();
        for (int i = tid; i < 64 * 32; i += 256) {
            int rr = i >> 5, c4 = (i & 31) * 4;
            *(float4*)&Ks[rr * QS_STRIDE + c4] =
                *(const float4*)&Kb[(size_t)(jb * 64 + rr) * DH + c4];
            *(float4*)&Vs[rr * QS_STRIDE + c4] =
                *(const float4*)&Vb[(size_t)(jb * 64 + rr) * DH + c4];
        }
        __syncthreads();

        float s4[4][4];
#pragma unroll
        for (int i = 0; i < 4; i++)
#pragma unroll
            for (int j = 0; j < 4; j++) s4[i][j] = 0.0f;

        for (int k = 0; k < DH; k += 4) {
            float4 q[4];
#pragma unroll
            for (int i = 0; i < 4; i++)
                q[i] = *(const float4*)&Qs[(tr * 4 + i) * QS_STRIDE + k];
#pragma unroll
            for (int j = 0; j < 4; j++) {
                float4 kv = *(const float4*)&Ks[(tc * 4 + j) * QS_STRIDE + k];
#pragma unroll
                for (int i = 0; i < 4; i++)
                    s4[i][j] += q[i].x * kv.x + q[i].y * kv.y +
                                q[i].z * kv.z + q[i].w * kv.w;
            }
        }

        const bool diag = (jb == qb);
#pragma unroll
        for (int i = 0; i < 4; i++)
#pragma unroll
            for (int j = 0; j < 4; j++) {
                s4[i][j] *= scale;
                if (diag && (tc * 4 + j) > (tr * 4 + i)) s4[i][j] = -1e30f;
            }

#pragma unroll
        for (int i = 0; i < 4; i++) {
            float tmax = fmaxf(fmaxf(s4[i][0], s4[i][1]), fmaxf(s4[i][2], s4[i][3]));
#pragma unroll
            for (int off = 1; off < 16; off <<= 1)
                tmax = fmaxf(tmax, __shfl_xor_sync(0xffffffffu, tmax, off));
            float mnew = fmaxf(m_i[i], tmax);
            float alpha = __expf(m_i[i] - mnew);
            m_i[i] = mnew;
            float rs = 0.0f;
#pragma unroll
            for (int j = 0; j < 4; j++) {
                float p = __expf(s4[i][j] - mnew);
                s4[i][j] = p;
                rs += p;
            }
#pragma unroll
            for (int off = 1; off < 16; off <<= 1)
                rs += __shfl_xor_sync(0xffffffffu, rs, off);
            l_i[i] = l_i[i] * alpha + rs;
#pragma unroll
            for (int c = 0; c < 8; c++) o[i][c] *= alpha;
        }

#pragma unroll
        for (int i = 0; i < 4; i++)
#pragma unroll
            for (int j = 0; j < 4; j++)
                Ps[(tr * 4 + i) * PS_STRIDE + tc * 4 + j] = s4[i][j];
        __syncthreads();

        for (int j = 0; j < 64; j++) {
            float p0 = Ps[(tr * 4 + 0) * PS_STRIDE + j];
            float p1 = Ps[(tr * 4 + 1) * PS_STRIDE + j];
            float p2 = Ps[(tr * 4 + 2) * PS_STRIDE + j];
            float p3 = Ps[(tr * 4 + 3) * PS_STRIDE + j];
            float4 v0 = *(const float4*)&Vs[j * QS_STRIDE + tc * 8];
            float4 v1 = *(const float4*)&Vs[j * QS_STRIDE + tc * 8 + 4];
            o[0][0] += p0 * v0.x; o[0][1] += p0 * v0.y; o[0][2] += p0 * v0.z; o[0][3] += p0 * v0.w;
            o[0][4] += p0 * v1.x; o[0][5] += p0 * v1.y; o[0][6] += p0 * v1.z; o[0][7] += p0 * v1.w;
            o[1][0] += p1 * v0.x; o[1][1] += p1 * v0.y; o[1][2] += p1 * v0.z; o[1][3] += p1 * v0.w;
            o[1][4] += p1 * v1.x; o[1][5] += p1 * v1.y; o[1][6] += p1 * v1.z; o[1][7] += p1 * v1.w;
            o[2][0] += p2 * v0.x; o[2][1] += p2 * v0.y; o[2][2] += p2 * v0.z; o[2][3] += p2 * v0.w;
            o[2][4] += p2 * v1.x; o[2][5] += p2 * v1.y; o[2][6] += p2 * v1.z; o[2][7] += p2 * v1.w;
            o[3][0] += p3 * v0.x; o[3][1] += p3 * v0.y; o[3][2] += p3 * v0.z; o[3][3] += p3 * v0.w;
            o[3][4] += p3 * v1.x; o[3][5] += p3 * v1.y; o[3][6] += p3 * v1.z; o[3][7] += p3 * v1.w;
        }
    }

#pragma unroll
    for (int i = 0; i < 4; i++) {
        int q = qb * 64 + tr * 4 + i;
        float invl = 1.0f / l_i[i];
        size_t off = ((size_t)(b * SEQ + q)) * DM + h * DH + tc * 8;
        float4 w0 = make_float4(o[i][0] * invl, o[i][1] * invl, o[i][2] * invl, o[i][3] * invl);
        float4 w1 = make_float4(o[i][4] * invl, o[i][5] * invl, o[i][6] * invl, o[i][7] * invl);
        *(float4*)&Y[off]     = w0;
        *(float4*)&Y[off + 4] = w1;
    }
}

// ---------------------------------------------------------------------------
extern "C" void kernel_launch(void* const* d_in, const int* in_sizes, int n_in,
                              void* d_out, int out_size)
{
    (void)in_sizes; (void)n_in; (void)out_size;
    const float* x   = (const float*)d_in[0];
    const int*   pos = (const int*)d_in[1];   // int32 or int64: detected in-kernel
    const float* Wq  = (const float*)d_in[2];
    const float* Wk  = (const float*)d_in[3];
    const float* Wv  = (const float*)d_in[4];
    const float* Wo  = (const float*)d_in[5];
    float* out = (float*)d_out;

    float *Qp, *Kp, *Vp, *Yp;
    cudaGetSymbolAddress((void**)&Qp, g_Q);
    cudaGetSymbolAddress((void**)&Kp, g_K);
    cudaGetSymbolAddress((void**)&Vp, g_V);
    cudaGetSymbolAddress((void**)&Yp, g_Y);

    dim3 ggrid(DM / 128, M_TOTAL / 128);   // (16, 64)
    gemm_tf32_kernel<<<ggrid, 256>>>(x, Wq, Qp, 2, pos);  // + fused RoPE
    gemm_tf32_kernel<<<ggrid, 256>>>(x, Wk, Kp, 2, pos);  // + fused RoPE
    gemm_tf32_kernel<<<ggrid, 256>>>(x, Wv, Vp, 1, pos);

    size_t smem = FLASH_SMEM_FLOATS * sizeof(float);
    cudaFuncSetAttribute(flash_kernel, cudaFuncAttributeMaxDynamicSharedMemorySize, (int)smem);
    flash_kernel<<<dim3(SEQ / 64, BHEADS), 256, smem>>>(Qp, Kp, Vp, Yp);

    gemm_tf32_kernel<<<ggrid, 256>>>(Yp, Wo, out, 0, pos);
}

// round 8
// speedup vs baseline: 2.9660x; 1.9038x over previous
#include <cuda_runtime.h>
#include <stdint.h>
#include <math.h>

#define DM   2048
#define NH   16
#define DH   128
#define SEQ  2048
#define BATCH 4
#define M_TOTAL (BATCH * SEQ)   // 8192
#define BHEADS  (BATCH * NH)    // 64
#define HALF    (DH / 2)        // 64

// Scratch (allocations forbidden; __device__ globals are the sanctioned path)
__device__ float g_Q[BHEADS * SEQ * DH];   // [b,h,s,d]
__device__ float g_K[BHEADS * SEQ * DH];
__device__ float g_V[BHEADS * SEQ * DH];
__device__ float g_Y[M_TOTAL * DM];        // [b,s,h*d]

__device__ __forceinline__ unsigned int f2tf32(float x) {
    unsigned int u;
    asm("cvt.rna.tf32.f32 %0, %1;" : "=r"(u) : "f"(x));
    return u;
}

__device__ __forceinline__ void mma_tf32(float4& d, const unsigned int a[4],
                                         const unsigned int b[2]) {
    asm volatile(
        "mma.sync.aligned.m16n8k8.row.col.f32.tf32.tf32.f32 "
        "{%0,%1,%2,%3}, {%4,%5,%6,%7}, {%8,%9}, {%0,%1,%2,%3};"
        : "+f"(d.x), "+f"(d.y), "+f"(d.z), "+f"(d.w)
        : "r"(a[0]), "r"(a[1]), "r"(a[2]), "r"(a[3]), "r"(b[0]), "r"(b[1]));
}

// ---------------------------------------------------------------------------
// TF32 tensor-core NT GEMM (unchanged from R7 passing version)
// ---------------------------------------------------------------------------
#define BK 16
#define SA 136

__global__ __launch_bounds__(256, 2)
void gemm_tf32_kernel(const float* __restrict__ A, const float* __restrict__ W,
                      float* __restrict__ out, int mode, const int* __restrict__ pos)
{
    __shared__ float As[2][BK * SA];
    __shared__ float Bs[2][BK * SA];

    const int tid  = threadIdx.x;
    const int lane = tid & 31;
    const int warp = tid >> 5;
    const int warpM = warp >> 1;
    const int warpN = warp & 1;
    const int bm = blockIdx.y * 128;
    const int bn = blockIdx.x * 128;

    const int lrow = tid >> 2;
    const int lc   = tid & 3;
    const float* Aptr = A + (size_t)(bm + lrow) * DM + lc * 4;
    const float* Wptr = W + (size_t)(bn + lrow) * DM + lc * 4;
    const int sw_st  = lc << 3;
    const int sbase0 = (lc * 4) * SA + (lrow ^ sw_st);
    const int sbase1 = (lc * 4) * SA + ((lrow + 64) ^ sw_st);

    float4 ra0, ra1, rb0, rb1;
    const int fr  = (lane >> 2);
    const int fc  = (lane & 3);

    float4 acc[2][8];
#pragma unroll
    for (int mt = 0; mt < 2; mt++)
#pragma unroll
        for (int nt = 0; nt < 8; nt++) acc[mt][nt] = make_float4(0.f, 0.f, 0.f, 0.f);

    ra0 = *(const float4*)(Aptr);
    ra1 = *(const float4*)(Aptr + (size_t)64 * DM);
    rb0 = *(const float4*)(Wptr);
    rb1 = *(const float4*)(Wptr + (size_t)64 * DM);

    for (int kt = 0; kt < DM; kt += BK) {
        const int buf = (kt >> 4) & 1;
        float* as = As[buf];
        float* bs = Bs[buf];
        as[sbase0 + 0 * SA] = __uint_as_float(f2tf32(ra0.x));
        as[sbase0 + 1 * SA] = __uint_as_float(f2tf32(ra0.y));
        as[sbase0 + 2 * SA] = __uint_as_float(f2tf32(ra0.z));
        as[sbase0 + 3 * SA] = __uint_as_float(f2tf32(ra0.w));
        as[sbase1 + 0 * SA] = __uint_as_float(f2tf32(ra1.x));
        as[sbase1 + 1 * SA] = __uint_as_float(f2tf32(ra1.y));
        as[sbase1 + 2 * SA] = __uint_as_float(f2tf32(ra1.z));
        as[sbase1 + 3 * SA] = __uint_as_float(f2tf32(ra1.w));
        bs[sbase0 + 0 * SA] = __uint_as_float(f2tf32(rb0.x));
        bs[sbase0 + 1 * SA] = __uint_as_float(f2tf32(rb0.y));
        bs[sbase0 + 2 * SA] = __uint_as_float(f2tf32(rb0.z));
        bs[sbase0 + 3 * SA] = __uint_as_float(f2tf32(rb0.w));
        bs[sbase1 + 0 * SA] = __uint_as_float(f2tf32(rb1.x));
        bs[sbase1 + 1 * SA] = __uint_as_float(f2tf32(rb1.y));
        bs[sbase1 + 2 * SA] = __uint_as_float(f2tf32(rb1.z));
        bs[sbase1 + 3 * SA] = __uint_as_float(f2tf32(rb1.w));
        __syncthreads();

        if (kt + BK < DM) {
            ra0 = *(const float4*)(Aptr + kt + BK);
            ra1 = *(const float4*)(Aptr + kt + BK + (size_t)64 * DM);
            rb0 = *(const float4*)(Wptr + kt + BK);
            rb1 = *(const float4*)(Wptr + kt + BK + (size_t)64 * DM);
        }

#pragma unroll
        for (int k8 = 0; k8 < 2; k8++) {
            const int k_lo = k8 * 8 + fc;
            const int k_hi = k_lo + 4;
            const int swl = ((k_lo >> 2) & 3) << 3;
            const int swh = ((k_hi >> 2) & 3) << 3;

            unsigned int af[2][4];
#pragma unroll
            for (int mt = 0; mt < 2; mt++) {
                const int r = warpM * 32 + mt * 16 + fr;
                af[mt][0] = __float_as_uint(as[k_lo * SA + (r ^ swl)]);
                af[mt][1] = __float_as_uint(as[k_lo * SA + ((r + 8) ^ swl)]);
                af[mt][2] = __float_as_uint(as[k_hi * SA + (r ^ swh)]);
                af[mt][3] = __float_as_uint(as[k_hi * SA + ((r + 8) ^ swh)]);
            }
#pragma unroll
            for (int nt = 0; nt < 8; nt++) {
                const int n = warpN * 64 + nt * 8 + fr;
                unsigned int bf[2];
                bf[0] = __float_as_uint(bs[k_lo * SA + (n ^ swl)]);
                bf[1] = __float_as_uint(bs[k_hi * SA + (n ^ swh)]);
                mma_tf32(acc[0][nt], af[0], bf);
                mma_tf32(acc[1][nt], af[1], bf);
            }
        }
        __syncthreads();
    }

    const bool is64 = (mode == 2) && (pos[1] == 0);
#pragma unroll
    for (int mt = 0; mt < 2; mt++) {
        const int gr0 = bm + warpM * 32 + mt * 16 + fr;
#pragma unroll
        for (int nt = 0; nt < 8; nt++) {
            const int gc = bn + warpN * 64 + nt * 8 + 2 * fc;
            float4 v = acc[mt][nt];
#pragma unroll
            for (int half = 0; half < 2; half++) {
                const int grow = gr0 + half * 8;
                float e = half ? v.z : v.x;
                float o = half ? v.w : v.y;
                if (mode == 0) {
                    *(float2*)(out + (size_t)grow * DM + gc) = make_float2(e, o);
                } else {
                    const int si = grow & (SEQ - 1), bi = grow >> 11;
                    const int head = gc >> 7, dd = gc & (DH - 1);
                    if (mode == 2) {
                        const int p = dd >> 1;
                        const int posv_i = is64 ? pos[2 * si] : pos[si];
                        const float inv_freq =
                            exp2f(-(float)p * (13.287712379549449f / 64.0f));
                        const float ang = (float)posv_i * inv_freq;
                        float sn, cs;
                        sincosf(ang, &sn, &cs);
                        const float e2 = e * cs - o * sn;
                        const float o2 = o * cs + e * sn;
                        e = e2; o = o2;
                    }
                    float* dst = out + ((((size_t)bi * NH + head) * SEQ + si) * DH + dd);
                    *(float2*)dst = make_float2(e, o);
                }
            }
        }
    }
}

// ---------------------------------------------------------------------------
// Tensor-core tf32 causal flash attention.
// Br=128, Bc=64, d=128. 256 threads = 8 warps; warp w owns rows [16w,16w+16).
// S = Q K^T and O += P V both via mma.m16n8k8.tf32. P staged per-warp in smem.
// Strides: Qs/Ks 132 (==4 mod 32), Vs 136 (==8 mod 32), Ps 68 -> all fragment
// LDS conflict-free.
// ---------------------------------------------------------------------------
#define QS_ST 132
#define KS_ST 132
#define VS_ST 136
#define PS_ST 68
#define FL_QS 0
#define FL_KS (128 * QS_ST)
#define FL_VS (FL_KS + 64 * KS_ST)
#define FL_PS (FL_VS + 64 * VS_ST)
#define FL_TOTAL (FL_PS + 128 * PS_ST)   // 42752 floats = 171,008 B

__global__ __launch_bounds__(256)
void flash_tc_kernel(const float* __restrict__ Q, const float* __restrict__ K,
                     const float* __restrict__ V, float* __restrict__ Y)
{
    extern __shared__ float sm[];
    float* Qs = sm + FL_QS;
    float* Ks = sm + FL_KS;
    float* Vs = sm + FL_VS;
    float* Ps = sm + FL_PS;

    const int qb = blockIdx.x;           // 0..15 (128-row Q block)
    const int bh = blockIdx.y;           // 0..63
    const int b  = bh >> 4, h = bh & 15;
    const int tid  = threadIdx.x;
    const int warp = tid >> 5;
    const int lane = tid & 31;
    const int fr = lane >> 2;            // 0..7
    const int fc = lane & 3;             // 0..3

    const float* Qb = Q + (size_t)bh * SEQ * DH;
    const float* Kb = K + (size_t)bh * SEQ * DH;
    const float* Vb = V + (size_t)bh * SEQ * DH;

    // load Q tile (128 x 128), tf32-rounded
    for (int i = tid; i < 128 * 32; i += 256) {
        const int r = i >> 5, c4 = (i & 31) * 4;
        float4 v = *(const float4*)&Qb[(size_t)(qb * 128 + r) * DH + c4];
        v.x = __uint_as_float(f2tf32(v.x));
        v.y = __uint_as_float(f2tf32(v.y));
        v.z = __uint_as_float(f2tf32(v.z));
        v.w = __uint_as_float(f2tf32(v.w));
        *(float4*)&Qs[r * QS_ST + c4] = v;
    }

    float4 oacc[16];
#pragma unroll
    for (int nt = 0; nt < 16; nt++) oacc[nt] = make_float4(0.f, 0.f, 0.f, 0.f);
    float m0 = -1e30f, m1 = -1e30f, l0 = 0.f, l1 = 0.f;
    const float scale = 0.08838834764831845f;   // 1/sqrt(128)

    const int arow0 = (16 * warp + fr) * QS_ST;
    const int arow1 = arow0 + 8 * QS_ST;
    const int prow0 = (16 * warp + fr) * PS_ST;
    const int prow1 = prow0 + 8 * PS_ST;
    const int r0g = qb * 128 + 16 * warp + fr;
    const int r1g = r0g + 8;

    const int nj = 2 * qb + 2;
    for (int jb = 0; jb < nj; jb++) {
        __syncthreads();   // Q visible (jb=0) / prev PV readers done (jb>0)
        for (int i = tid; i < 64 * 32; i += 256) {
            const int r = i >> 5, c4 = (i & 31) * 4;
            float4 kv = *(const float4*)&Kb[(size_t)(jb * 64 + r) * DH + c4];
            float4 vv = *(const float4*)&Vb[(size_t)(jb * 64 + r) * DH + c4];
            kv.x = __uint_as_float(f2tf32(kv.x));
            kv.y = __uint_as_float(f2tf32(kv.y));
            kv.z = __uint_as_float(f2tf32(kv.z));
            kv.w = __uint_as_float(f2tf32(kv.w));
            vv.x = __uint_as_float(f2tf32(vv.x));
            vv.y = __uint_as_float(f2tf32(vv.y));
            vv.z = __uint_as_float(f2tf32(vv.z));
            vv.w = __uint_as_float(f2tf32(vv.w));
            *(float4*)&Ks[r * KS_ST + c4] = kv;
            *(float4*)&Vs[r * VS_ST + c4] = vv;
        }
        __syncthreads();

        // ---- S = Q K^T  (warp tile 16 x 64) ----
        float4 sacc[8];
#pragma unroll
        for (int nt = 0; nt < 8; nt++) sacc[nt] = make_float4(0.f, 0.f, 0.f, 0.f);

#pragma unroll 4
        for (int ks = 0; ks < 16; ks++) {
            const int k0 = ks * 8 + fc;
            unsigned int af[4];
            af[0] = __float_as_uint(Qs[arow0 + k0]);
            af[1] = __float_as_uint(Qs[arow1 + k0]);
            af[2] = __float_as_uint(Qs[arow0 + k0 + 4]);
            af[3] = __float_as_uint(Qs[arow1 + k0 + 4]);
#pragma unroll
            for (int nt = 0; nt < 8; nt++) {
                unsigned int bf[2];
                bf[0] = __float_as_uint(Ks[(8 * nt + fr) * KS_ST + k0]);
                bf[1] = __float_as_uint(Ks[(8 * nt + fr) * KS_ST + k0 + 4]);
                mma_tf32(sacc[nt], af, bf);
            }
        }

        // ---- scale + causal mask ----
        const bool domask = (jb * 64 + 63) > (qb * 128 + 16 * warp);
#pragma unroll
        for (int nt = 0; nt < 8; nt++) {
            const int c0 = jb * 64 + 8 * nt + 2 * fc;
            const int c1 = c0 + 1;
            sacc[nt].x *= scale; sacc[nt].y *= scale;
            sacc[nt].z *= scale; sacc[nt].w *= scale;
            if (domask) {
                if (c0 > r0g) sacc[nt].x = -1e30f;
                if (c1 > r0g) sacc[nt].y = -1e30f;
                if (c0 > r1g) sacc[nt].z = -1e30f;
                if (c1 > r1g) sacc[nt].w = -1e30f;
            }
        }

        // ---- online softmax (rows fr and fr+8, reduction within quad) ----
        float mx0 = -1e30f, mx1 = -1e30f;
#pragma unroll
        for (int nt = 0; nt < 8; nt++) {
            mx0 = fmaxf(mx0, fmaxf(sacc[nt].x, sacc[nt].y));
            mx1 = fmaxf(mx1, fmaxf(sacc[nt].z, sacc[nt].w));
        }
        mx0 = fmaxf(mx0, __shfl_xor_sync(0xffffffffu, mx0, 1));
        mx0 = fmaxf(mx0, __shfl_xor_sync(0xffffffffu, mx0, 2));
        mx1 = fmaxf(mx1, __shfl_xor_sync(0xffffffffu, mx1, 1));
        mx1 = fmaxf(mx1, __shfl_xor_sync(0xffffffffu, mx1, 2));

        const float mn0 = fmaxf(m0, mx0);
        const float mn1 = fmaxf(m1, mx1);
        const float alpha0 = __expf(m0 - mn0);
        const float alpha1 = __expf(m1 - mn1);
        m0 = mn0; m1 = mn1;

        float rs0 = 0.f, rs1 = 0.f;
#pragma unroll
        for (int nt = 0; nt < 8; nt++) {
            sacc[nt].x = __expf(sacc[nt].x - mn0);
            sacc[nt].y = __expf(sacc[nt].y - mn0);
            sacc[nt].z = __expf(sacc[nt].z - mn1);
            sacc[nt].w = __expf(sacc[nt].w - mn1);
            rs0 += sacc[nt].x + sacc[nt].y;
            rs1 += sacc[nt].z + sacc[nt].w;
        }
        rs0 += __shfl_xor_sync(0xffffffffu, rs0, 1);
        rs0 += __shfl_xor_sync(0xffffffffu, rs0, 2);
        rs1 += __shfl_xor_sync(0xffffffffu, rs1, 1);
        rs1 += __shfl_xor_sync(0xffffffffu, rs1, 2);
        l0 = l0 * alpha0 + rs0;
        l1 = l1 * alpha1 + rs1;

#pragma unroll
        for (int nt = 0; nt < 16; nt++) {
            oacc[nt].x *= alpha0; oacc[nt].y *= alpha0;
            oacc[nt].z *= alpha1; oacc[nt].w *= alpha1;
        }

        // ---- stage P (own warp rows only) ----
#pragma unroll
        for (int nt = 0; nt < 8; nt++) {
            const int cb = 8 * nt + 2 * fc;
            *(float2*)&Ps[prow0 + cb] = make_float2(
                __uint_as_float(f2tf32(sacc[nt].x)),
                __uint_as_float(f2tf32(sacc[nt].y)));
            *(float2*)&Ps[prow1 + cb] = make_float2(
                __uint_as_float(f2tf32(sacc[nt].z)),
                __uint_as_float(f2tf32(sacc[nt].w)));
        }
        __syncwarp();

        // ---- O += P V  (warp tile 16 x 128, K-dim 64) ----
#pragma unroll 4
        for (int ks = 0; ks < 8; ks++) {
            const int k0 = ks * 8 + fc;
            unsigned int af[4];
            af[0] = __float_as_uint(Ps[prow0 + k0]);
            af[1] = __float_as_uint(Ps[prow1 + k0]);
            af[2] = __float_as_uint(Ps[prow0 + k0 + 4]);
            af[3] = __float_as_uint(Ps[prow1 + k0 + 4]);
#pragma unroll
            for (int nt = 0; nt < 16; nt++) {
                unsigned int bf[2];
                bf[0] = __float_as_uint(Vs[k0 * VS_ST + 8 * nt + fr]);
                bf[1] = __float_as_uint(Vs[(k0 + 4) * VS_ST + 8 * nt + fr]);
                mma_tf32(oacc[nt], af, bf);
            }
        }
        __syncwarp();   // P reads done before next iteration overwrites
    }

    // ---- epilogue: normalize, write to Y [b, s, h*128+d] ----
    const float inv0 = 1.0f / l0;
    const float inv1 = 1.0f / l1;
    const size_t y0 = ((size_t)(b * SEQ + r0g)) * DM + h * DH;
    const size_t y1 = ((size_t)(b * SEQ + r1g)) * DM + h * DH;
#pragma unroll
    for (int nt = 0; nt < 16; nt++) {
        const int cb = 8 * nt + 2 * fc;
        *(float2*)&Y[y0 + cb] = make_float2(oacc[nt].x * inv0, oacc[nt].y * inv0);
        *(float2*)&Y[y1 + cb] = make_float2(oacc[nt].z * inv1, oacc[nt].w * inv1);
    }
}

// ---------------------------------------------------------------------------
extern "C" void kernel_launch(void* const* d_in, const int* in_sizes, int n_in,
                              void* d_out, int out_size)
{
    (void)in_sizes; (void)n_in; (void)out_size;
    const float* x   = (const float*)d_in[0];
    const int*   pos = (const int*)d_in[1];   // int32 or int64: detected in-kernel
    const float* Wq  = (const float*)d_in[2];
    const float* Wk  = (const float*)d_in[3];
    const float* Wv  = (const float*)d_in[4];
    const float* Wo  = (const float*)d_in[5];
    float* out = (float*)d_out;

    float *Qp, *Kp, *Vp, *Yp;
    cudaGetSymbolAddress((void**)&Qp, g_Q);
    cudaGetSymbolAddress((void**)&Kp, g_K);
    cudaGetSymbolAddress((void**)&Vp, g_V);
    cudaGetSymbolAddress((void**)&Yp, g_Y);

    dim3 ggrid(DM / 128, M_TOTAL / 128);   // (16, 64)
    gemm_tf32_kernel<<<ggrid, 256>>>(x, Wq, Qp, 2, pos);  // + fused RoPE
    gemm_tf32_kernel<<<ggrid, 256>>>(x, Wk, Kp, 2, pos);  // + fused RoPE
    gemm_tf32_kernel<<<ggrid, 256>>>(x, Wv, Vp, 1, pos);

    size_t fsmem = (size_t)FL_TOTAL * sizeof(float);      // 171,008 B
    cudaFuncSetAttribute(flash_tc_kernel,
                         cudaFuncAttributeMaxDynamicSharedMemorySize, (int)fsmem);
    flash_tc_kernel<<<dim3(SEQ / 128, BHEADS), 256, fsmem>>>(Qp, Kp, Vp, Yp);

    gemm_tf32_kernel<<<ggrid, 256>>>(Yp, Wo, out, 0, pos);
}

// round 11
// speedup vs baseline: 3.5767x; 1.2059x over previous
#include <cuda_runtime.h>
#include <stdint.h>
#include <math.h>

#define DM   2048
#define NH   16
#define DH   128
#define SEQ  2048
#define BATCH 4
#define M_TOTAL (BATCH * SEQ)   // 8192
#define BHEADS  (BATCH * NH)    // 64
#define HALF    (DH / 2)        // 64

// Scratch (allocations forbidden; __device__ globals are the sanctioned path)
__device__ float g_Q[BHEADS * SEQ * DH];   // [b,h,s,d]
__device__ float g_K[BHEADS * SEQ * DH];
__device__ float g_V[BHEADS * SEQ * DH];
__device__ float g_Y[M_TOTAL * DM];        // [b,s,h*d]

__device__ __forceinline__ unsigned int f2tf32(float x) {
    unsigned int u;
    asm("cvt.rna.tf32.f32 %0, %1;" : "=r"(u) : "f"(x));
    return u;
}

__device__ __forceinline__ void mma_tf32(float4& d, const unsigned int a[4],
                                         const unsigned int b[2]) {
    asm volatile(
        "mma.sync.aligned.m16n8k8.row.col.f32.tf32.tf32.f32 "
        "{%0,%1,%2,%3}, {%4,%5,%6,%7}, {%8,%9}, {%0,%1,%2,%3};"
        : "+f"(d.x), "+f"(d.y), "+f"(d.z), "+f"(d.w)
        : "r"(a[0]), "r"(a[1]), "r"(a[2]), "r"(a[3]), "r"(b[0]), "r"(b[1]));
}

__device__ __forceinline__ void ldsm_x4(unsigned int& r0, unsigned int& r1,
                                        unsigned int& r2, unsigned int& r3,
                                        unsigned int addr) {
    asm volatile("ldmatrix.sync.aligned.m8n8.x4.shared.b16 {%0,%1,%2,%3}, [%4];"
                 : "=r"(r0), "=r"(r1), "=r"(r2), "=r"(r3) : "r"(addr));
}

__device__ __forceinline__ unsigned int smem_u32(const void* p) {
    return (unsigned int)__cvta_generic_to_shared(p);
}

// ---------------------------------------------------------------------------
// TF32 tensor-core NT GEMM: C[M,N] = A[M,K] * W[N,K]^T  (M=8192, N=K=2048)
// Block 128x128, BK=16, 256 threads (8 warps as 4Mx2N), warp tile 32x64.
// Smem [row][k] (k contiguous, 16 f32/row), 16B-chunk XOR swizzle:
//   chunk_pos(row, c) = row*4 + (c ^ ((row>>1)&3)),  c = k/4
// -> STS.128 conflict-free, every ldmatrix 8-row tile conflict-free.
// Fragments loaded via ldmatrix.x4 (12 LDSM/warp/BK vs 48 scalar LDS before).
// mode 0: plain row-major; mode 1: scatter [b,h,s,d]; mode 2: scatter+RoPE
// ---------------------------------------------------------------------------
#define BK 16

__global__ __launch_bounds__(256, 2)
void gemm_tf32_kernel(const float* __restrict__ A, const float* __restrict__ W,
                      float* __restrict__ out, int mode, const int* __restrict__ pos)
{
    __shared__ __align__(16) float As[2][128 * BK];
    __shared__ __align__(16) float Bs[2][128 * BK];

    const int tid  = threadIdx.x;
    const int lane = tid & 31;
    const int warp = tid >> 5;
    const int warpM = warp >> 1;     // 0..3
    const int warpN = warp & 1;      // 0..1
    const int bm = blockIdx.y * 128;
    const int bn = blockIdx.x * 128;

    // loader: thread -> rows (tid>>2) and (tid>>2)+64, k-chunk (tid&3)
    const int lrow = tid >> 2;       // 0..63
    const int lc   = tid & 3;        // chunk 0..3
    const float* Aptr = A + (size_t)(bm + lrow) * DM + lc * 4;
    const float* Wptr = W + (size_t)(bn + lrow) * DM + lc * 4;
    const int swz    = (lrow >> 1) & 3;                 // same for lrow+64
    const int st0 = (lrow * 4 + (lc ^ swz)) * 4;        // float index
    const int st1 = ((lrow + 64) * 4 + (lc ^ swz)) * 4;

    float4 ra0, ra1, rb0, rb1;

    // ldmatrix source addresses (byte offsets into tile, without buffer base)
    // A tiles (16 rows x k8): row = warpM*32 + mt*16 + (lane&15), chunk = 2*k8 + (lane>>4)
    const int a_row0 = warpM * 32 + (lane & 15);
    const int a_hi   = lane >> 4;                       // 0/1
    // B tiles (nt pair p): row = warpN*64 + 16p + ((lane>>4)<<3) + (lane&7),
    //                      chunk = 2*k8 + ((lane>>3)&1)
    const int b_rowl = ((lane >> 4) << 3) + (lane & 7);
    const int b_hi   = (lane >> 3) & 1;

    float4 acc[2][8];
#pragma unroll
    for (int mt = 0; mt < 2; mt++)
#pragma unroll
        for (int nt = 0; nt < 8; nt++) acc[mt][nt] = make_float4(0.f, 0.f, 0.f, 0.f);

    const unsigned int asm_base[2] = { smem_u32(As[0]), smem_u32(As[1]) };
    const unsigned int bsm_base[2] = { smem_u32(Bs[0]), smem_u32(Bs[1]) };

    // prologue
    ra0 = *(const float4*)(Aptr);
    ra1 = *(const float4*)(Aptr + (size_t)64 * DM);
    rb0 = *(const float4*)(Wptr);
    rb1 = *(const float4*)(Wptr + (size_t)64 * DM);

    for (int kt = 0; kt < DM; kt += BK) {
        const int buf = (kt >> 4) & 1;
        float* as = As[buf];
        float* bs = Bs[buf];
        *(float4*)&as[st0] = make_float4(
            __uint_as_float(f2tf32(ra0.x)), __uint_as_float(f2tf32(ra0.y)),
            __uint_as_float(f2tf32(ra0.z)), __uint_as_float(f2tf32(ra0.w)));
        *(float4*)&as[st1] = make_float4(
            __uint_as_float(f2tf32(ra1.x)), __uint_as_float(f2tf32(ra1.y)),
            __uint_as_float(f2tf32(ra1.z)), __uint_as_float(f2tf32(ra1.w)));
        *(float4*)&bs[st0] = make_float4(
            __uint_as_float(f2tf32(rb0.x)), __uint_as_float(f2tf32(rb0.y)),
            __uint_as_float(f2tf32(rb0.z)), __uint_as_float(f2tf32(rb0.w)));
        *(float4*)&bs[st1] = make_float4(
            __uint_as_float(f2tf32(rb1.x)), __uint_as_float(f2tf32(rb1.y)),
            __uint_as_float(f2tf32(rb1.z)), __uint_as_float(f2tf32(rb1.w)));
        __syncthreads();

        if (kt + BK < DM) {
            ra0 = *(const float4*)(Aptr + kt + BK);
            ra1 = *(const float4*)(Aptr + kt + BK + (size_t)64 * DM);
            rb0 = *(const float4*)(Wptr + kt + BK);
            rb1 = *(const float4*)(Wptr + kt + BK + (size_t)64 * DM);
        }

        const unsigned int ab = asm_base[buf];
        const unsigned int bb = bsm_base[buf];
#pragma unroll
        for (int k8 = 0; k8 < 2; k8++) {
            unsigned int af[2][4];
#pragma unroll
            for (int mt = 0; mt < 2; mt++) {
                const int row = a_row0 + mt * 16;
                const int c   = (2 * k8 + a_hi) ^ ((row >> 1) & 3);
                ldsm_x4(af[mt][0], af[mt][1], af[mt][2], af[mt][3],
                        ab + (unsigned)((row * 4 + c) << 4));
            }
#pragma unroll
            for (int p = 0; p < 4; p++) {
                const int row = warpN * 64 + 16 * p + b_rowl;
                const int c   = (2 * k8 + b_hi) ^ ((row >> 1) & 3);
                unsigned int r0, r1, r2, r3;
                ldsm_x4(r0, r1, r2, r3, bb + (unsigned)((row * 4 + c) << 4));
                unsigned int bf0[2] = { r0, r1 };
                unsigned int bf1[2] = { r2, r3 };
                mma_tf32(acc[0][2 * p],     af[0], bf0);
                mma_tf32(acc[1][2 * p],     af[1], bf0);
                mma_tf32(acc[0][2 * p + 1], af[0], bf1);
                mma_tf32(acc[1][2 * p + 1], af[1], bf1);
            }
        }
        __syncthreads();
    }

    const int fr = lane >> 2;
    const int fc = lane & 3;
    const bool is64 = (mode == 2) && (pos[1] == 0);
#pragma unroll
    for (int mt = 0; mt < 2; mt++) {
        const int gr0 = bm + warpM * 32 + mt * 16 + fr;
#pragma unroll
        for (int nt = 0; nt < 8; nt++) {
            const int gc = bn + warpN * 64 + nt * 8 + 2 * fc;
            float4 v = acc[mt][nt];
#pragma unroll
            for (int half = 0; half < 2; half++) {
                const int grow = gr0 + half * 8;
                float e = half ? v.z : v.x;
                float o = half ? v.w : v.y;
                if (mode == 0) {
                    *(float2*)(out + (size_t)grow * DM + gc) = make_float2(e, o);
                } else {
                    const int si = grow & (SEQ - 1), bi = grow >> 11;
                    const int head = gc >> 7, dd = gc & (DH - 1);
                    if (mode == 2) {
                        const int p = dd >> 1;
                        const int posv_i = is64 ? pos[2 * si] : pos[si];
                        const float inv_freq =
                            exp2f(-(float)p * (13.287712379549449f / 64.0f));
                        const float ang = (float)posv_i * inv_freq;
                        float sn, cs;
                        sincosf(ang, &sn, &cs);
                        const float e2 = e * cs - o * sn;
                        const float o2 = o * cs + e * sn;
                        e = e2; o = o2;
                    }
                    float* dst = out + ((((size_t)bi * NH + head) * SEQ + si) * DH + dd);
                    *(float2*)dst = make_float2(e, o);
                }
            }
        }
    }
}

// ---------------------------------------------------------------------------
// Tensor-core tf32 causal flash attention (Br=128, Bc=64, d=128, 8 warps).
// S=QK^T and PV via mma.m16n8k8.tf32. Q/K/P fragments via ldmatrix (strides
// 132/132/68 floats = odd 16B-chunk counts -> (row+chunk)%8 distinct ->
// conflict-free LDSM). V fragments remain scalar LDS (stride 136, conflict-free).
// ---------------------------------------------------------------------------
#define QS_ST 132
#define KS_ST 132
#define VS_ST 136
#define PS_ST 68
#define FL_QS 0
#define FL_KS (128 * QS_ST)
#define FL_VS (FL_KS + 64 * KS_ST)
#define FL_PS (FL_VS + 64 * VS_ST)
#define FL_TOTAL (FL_PS + 128 * PS_ST)   // 42752 floats = 171,008 B

__global__ __launch_bounds__(256)
void flash_tc_kernel(const float* __restrict__ Q, const float* __restrict__ K,
                     const float* __restrict__ V, float* __restrict__ Y)
{
    extern __shared__ float sm[];
    float* Qs = sm + FL_QS;
    float* Ks = sm + FL_KS;
    float* Vs = sm + FL_VS;
    float* Ps = sm + FL_PS;

    const int qb = blockIdx.x;           // 0..15 (128-row Q block)
    const int bh = blockIdx.y;           // 0..63
    const int b  = bh >> 4, h = bh & 15;
    const int tid  = threadIdx.x;
    const int warp = tid >> 5;
    const int lane = tid & 31;
    const int fr = lane >> 2;            // 0..7
    const int fc = lane & 3;             // 0..3

    const float* Qb = Q + (size_t)bh * SEQ * DH;
    const float* Kb = K + (size_t)bh * SEQ * DH;
    const float* Vb = V + (size_t)bh * SEQ * DH;

    // load Q tile (128 x 128), tf32-rounded
    for (int i = tid; i < 128 * 32; i += 256) {
        const int r = i >> 5, c4 = (i & 31) * 4;
        float4 v = *(const float4*)&Qb[(size_t)(qb * 128 + r) * DH + c4];
        v.x = __uint_as_float(f2tf32(v.x));
        v.y = __uint_as_float(f2tf32(v.y));
        v.z = __uint_as_float(f2tf32(v.z));
        v.w = __uint_as_float(f2tf32(v.w));
        *(float4*)&Qs[r * QS_ST + c4] = v;
    }

    float4 oacc[16];
#pragma unroll
    for (int nt = 0; nt < 16; nt++) oacc[nt] = make_float4(0.f, 0.f, 0.f, 0.f);
    float m0 = -1e30f, m1 = -1e30f, l0 = 0.f, l1 = 0.f;
    const float scale = 0.08838834764831845f;   // 1/sqrt(128)

    const int prow0 = (16 * warp + fr) * PS_ST;
    const int prow1 = prow0 + 8 * PS_ST;
    const int r0g = qb * 128 + 16 * warp + fr;
    const int r1g = r0g + 8;

    // LDSM base addresses (bytes). Q/P A-tiles: row = 16*warp + (lane&15),
    // chunk-within-k8 = lane>>4. K B-tiles: row = 16p + ((lane>>4)<<3)+(lane&7),
    // chunk = (lane>>3)&1.
    const int a_rowl = 16 * warp + (lane & 15);
    const unsigned int q_base = smem_u32(Qs) +
        (unsigned)((a_rowl * QS_ST + (lane >> 4) * 4) << 2);
    const unsigned int p_base = smem_u32(Ps) +
        (unsigned)((a_rowl * PS_ST + (lane >> 4) * 4) << 2);
    const int b_rowl = ((lane >> 4) << 3) + (lane & 7);
    const int b_hi4  = ((lane >> 3) & 1) * 4;
    unsigned int k_base[4];
#pragma unroll
    for (int p = 0; p < 4; p++)
        k_base[p] = smem_u32(Ks) + (unsigned)(((16 * p + b_rowl) * KS_ST + b_hi4) << 2);

    const int nj = 2 * qb + 2;
    for (int jb = 0; jb < nj; jb++) {
        __syncthreads();   // Q visible (jb=0) / prev PV readers done (jb>0)
        for (int i = tid; i < 64 * 32; i += 256) {
            const int r = i >> 5, c4 = (i & 31) * 4;
            float4 kv = *(const float4*)&Kb[(size_t)(jb * 64 + r) * DH + c4];
            float4 vv = *(const float4*)&Vb[(size_t)(jb * 64 + r) * DH + c4];
            kv.x = __uint_as_float(f2tf32(kv.x));
            kv.y = __uint_as_float(f2tf32(kv.y));
            kv.z = __uint_as_float(f2tf32(kv.z));
            kv.w = __uint_as_float(f2tf32(kv.w));
            vv.x = __uint_as_float(f2tf32(vv.x));
            vv.y = __uint_as_float(f2tf32(vv.y));
            vv.z = __uint_as_float(f2tf32(vv.z));
            vv.w = __uint_as_float(f2tf32(vv.w));
            *(float4*)&Ks[r * KS_ST + c4] = kv;
            *(float4*)&Vs[r * VS_ST + c4] = vv;
        }
        __syncthreads();

        // ---- S = Q K^T  (warp tile 16 x 64) ----
        float4 sacc[8];
#pragma unroll
        for (int nt = 0; nt < 8; nt++) sacc[nt] = make_float4(0.f, 0.f, 0.f, 0.f);

#pragma unroll 4
        for (int ks = 0; ks < 16; ks++) {
            unsigned int af[4];
            ldsm_x4(af[0], af[1], af[2], af[3], q_base + 32u * ks);
#pragma unroll
            for (int p = 0; p < 4; p++) {
                unsigned int r0, r1, r2, r3;
                ldsm_x4(r0, r1, r2, r3, k_base[p] + 32u * ks);
                unsigned int bf0[2] = { r0, r1 };
                unsigned int bf1[2] = { r2, r3 };
                mma_tf32(sacc[2 * p],     af, bf0);
                mma_tf32(sacc[2 * p + 1], af, bf1);
            }
        }

        // ---- scale + causal mask ----
        const bool domask = (jb * 64 + 63) > (qb * 128 + 16 * warp);
#pragma unroll
        for (int nt = 0; nt < 8; nt++) {
            const int c0 = jb * 64 + 8 * nt + 2 * fc;
            const int c1 = c0 + 1;
            sacc[nt].x *= scale; sacc[nt].y *= scale;
            sacc[nt].z *= scale; sacc[nt].w *= scale;
            if (domask) {
                if (c0 > r0g) sacc[nt].x = -1e30f;
                if (c1 > r0g) sacc[nt].y = -1e30f;
                if (c0 > r1g) sacc[nt].z = -1e30f;
                if (c1 > r1g) sacc[nt].w = -1e30f;
            }
        }

        // ---- online softmax (rows fr and fr+8, reduction within quad) ----
        float mx0 = -1e30f, mx1 = -1e30f;
#pragma unroll
        for (int nt = 0; nt < 8; nt++) {
            mx0 = fmaxf(mx0, fmaxf(sacc[nt].x, sacc[nt].y));
            mx1 = fmaxf(mx1, fmaxf(sacc[nt].z, sacc[nt].w));
        }
        mx0 = fmaxf(mx0, __shfl_xor_sync(0xffffffffu, mx0, 1));
        mx0 = fmaxf(mx0, __shfl_xor_sync(0xffffffffu, mx0, 2));
        mx1 = fmaxf(mx1, __shfl_xor_sync(0xffffffffu, mx1, 1));
        mx1 = fmaxf(mx1, __shfl_xor_sync(0xffffffffu, mx1, 2));

        const float mn0 = fmaxf(m0, mx0);
        const float mn1 = fmaxf(m1, mx1);
        const float alpha0 = __expf(m0 - mn0);
        const float alpha1 = __expf(m1 - mn1);
        m0 = mn0; m1 = mn1;

        float rs0 = 0.f, rs1 = 0.f;
#pragma unroll
        for (int nt = 0; nt < 8; nt++) {
            sacc[nt].x = __expf(sacc[nt].x - mn0);
            sacc[nt].y = __expf(sacc[nt].y - mn0);
            sacc[nt].z = __expf(sacc[nt].z - mn1);
            sacc[nt].w = __expf(sacc[nt].w - mn1);
            rs0 += sacc[nt].x + sacc[nt].y;
            rs1 += sacc[nt].z + sacc[nt].w;
        }
        rs0 += __shfl_xor_sync(0xffffffffu, rs0, 1);
        rs0 += __shfl_xor_sync(0xffffffffu, rs0, 2);
        rs1 += __shfl_xor_sync(0xffffffffu, rs1, 1);
        rs1 += __shfl_xor_sync(0xffffffffu, rs1, 2);
        l0 = l0 * alpha0 + rs0;
        l1 = l1 * alpha1 + rs1;

#pragma unroll
        for (int nt = 0; nt < 16; nt++) {
            oacc[nt].x *= alpha0; oacc[nt].y *= alpha0;
            oacc[nt].z *= alpha1; oacc[nt].w *= alpha1;
        }

        // ---- stage P (own warp rows only) ----
#pragma unroll
        for (int nt = 0; nt < 8; nt++) {
            const int cb = 8 * nt + 2 * fc;
            *(float2*)&Ps[prow0 + cb] = make_float2(
                __uint_as_float(f2tf32(sacc[nt].x)),
                __uint_as_float(f2tf32(sacc[nt].y)));
            *(float2*)&Ps[prow1 + cb] = make_float2(
                __uint_as_float(f2tf32(sacc[nt].z)),
                __uint_as_float(f2tf32(sacc[nt].w)));
        }
        __syncwarp();

        // ---- O += P V  (warp tile 16 x 128, K-dim 64) ----
#pragma unroll 4
        for (int ks = 0; ks < 8; ks++) {
            const int k0 = ks * 8 + fc;
            unsigned int af[4];
            ldsm_x4(af[0], af[1], af[2], af[3], p_base + 32u * ks);
#pragma unroll
            for (int nt = 0; nt < 16; nt++) {
                unsigned int bf[2];
                bf[0] = __float_as_uint(Vs[k0 * VS_ST + 8 * nt + fr]);
                bf[1] = __float_as_uint(Vs[(k0 + 4) * VS_ST + 8 * nt + fr]);
                mma_tf32(oacc[nt], af, bf);
            }
        }
        __syncwarp();   // P reads done before next iteration overwrites
    }

    // ---- epilogue: normalize, write to Y [b, s, h*128+d] ----
    const float inv0 = 1.0f / l0;
    const float inv1 = 1.0f / l1;
    const size_t y0 = ((size_t)(b * SEQ + r0g)) * DM + h * DH;
    const size_t y1 = ((size_t)(b * SEQ + r1g)) * DM + h * DH;
#pragma unroll
    for (int nt = 0; nt < 16; nt++) {
        const int cb = 8 * nt + 2 * fc;
        *(float2*)&Y[y0 + cb] = make_float2(oacc[nt].x * inv0, oacc[nt].y * inv0);
        *(float2*)&Y[y1 + cb] = make_float2(oacc[nt].z * inv1, oacc[nt].w * inv1);
    }
}

// ---------------------------------------------------------------------------
extern "C" void kernel_launch(void* const* d_in, const int* in_sizes, int n_in,
                              void* d_out, int out_size)
{
    (void)in_sizes; (void)n_in; (void)out_size;
    const float* x   = (const float*)d_in[0];
    const int*   pos = (const int*)d_in[1];   // int32 or int64: detected in-kernel
    const float* Wq  = (const float*)d_in[2];
    const float* Wk  = (const float*)d_in[3];
    const float* Wv  = (const float*)d_in[4];
    const float* Wo  = (const float*)d_in[5];
    float* out = (float*)d_out;

    float *Qp, *Kp, *Vp, *Yp;
    cudaGetSymbolAddress((void**)&Qp, g_Q);
    cudaGetSymbolAddress((void**)&Kp, g_K);
    cudaGetSymbolAddress((void**)&Vp, g_V);
    cudaGetSymbolAddress((void**)&Yp, g_Y);

    dim3 ggrid(DM / 128, M_TOTAL / 128);   // (16, 64)
    gemm_tf32_kernel<<<ggrid, 256>>>(x, Wq, Qp, 2, pos);  // + fused RoPE
    gemm_tf32_kernel<<<ggrid, 256>>>(x, Wk, Kp, 2, pos);  // + fused RoPE
    gemm_tf32_kernel<<<ggrid, 256>>>(x, Wv, Vp, 1, pos);

    size_t fsmem = (size_t)FL_TOTAL * sizeof(float);      // 171,008 B
    cudaFuncSetAttribute(flash_tc_kernel,
                         cudaFuncAttributeMaxDynamicSharedMemorySize, (int)fsmem);
    flash_tc_kernel<<<dim3(SEQ / 128, BHEADS), 256, fsmem>>>(Qp, Kp, Vp, Yp);

    gemm_tf32_kernel<<<ggrid, 256>>>(Yp, Wo, out, 0, pos);
}

// round 12
// speedup vs baseline: 4.9598x; 1.3867x over previous
#include <cuda_runtime.h>
#include <cuda_fp16.h>
#include <stdint.h>
#include <math.h>

#define DM   2048
#define NH   16
#define DH   128
#define SEQ  2048
#define BATCH 4
#define M_TOTAL (BATCH * SEQ)   // 8192
#define BHEADS  (BATCH * NH)    // 64

// Scratch (allocations forbidden; __device__ globals are the sanctioned path)
__device__ __half g_Q[BHEADS * SEQ * DH];   // [b,h,s,d]
__device__ __half g_K[BHEADS * SEQ * DH];
__device__ __half g_V[BHEADS * SEQ * DH];
__device__ __half g_Y[M_TOTAL * DM];        // [b,s,h*d]

__device__ __forceinline__ void mma_f16(float4& d, const unsigned int a[4],
                                        unsigned int b0, unsigned int b1) {
    asm volatile(
        "mma.sync.aligned.m16n8k16.row.col.f32.f16.f16.f32 "
        "{%0,%1,%2,%3}, {%4,%5,%6,%7}, {%8,%9}, {%0,%1,%2,%3};"
        : "+f"(d.x), "+f"(d.y), "+f"(d.z), "+f"(d.w)
        : "r"(a[0]), "r"(a[1]), "r"(a[2]), "r"(a[3]), "r"(b0), "r"(b1));
}

__device__ __forceinline__ void ldsm_x4(unsigned int& r0, unsigned int& r1,
                                        unsigned int& r2, unsigned int& r3,
                                        unsigned int addr) {
    asm volatile("ldmatrix.sync.aligned.m8n8.x4.shared.b16 {%0,%1,%2,%3}, [%4];"
                 : "=r"(r0), "=r"(r1), "=r"(r2), "=r"(r3) : "r"(addr));
}

__device__ __forceinline__ void ldsm_x4_trans(unsigned int& r0, unsigned int& r1,
                                              unsigned int& r2, unsigned int& r3,
                                              unsigned int addr) {
    asm volatile("ldmatrix.sync.aligned.m8n8.x4.trans.shared.b16 {%0,%1,%2,%3}, [%4];"
                 : "=r"(r0), "=r"(r1), "=r"(r2), "=r"(r3) : "r"(addr));
}

__device__ __forceinline__ unsigned int smem_u32(const void* p) {
    return (unsigned int)__cvta_generic_to_shared(p);
}

// ---------------------------------------------------------------------------
// FP16 tensor-core NT GEMM: C[M,N] = A[M,K] * W[N,K]^T  (M=8192, N=K=2048)
// Block 128x128, BK=32 halves, 256 threads (8 warps 4Mx2N), warp tile 32x64,
// mma.m16n8k16.f16 with f32 accum. Smem [row][32 halves], 16B-chunk swizzle
// c^((row>>1)&3): STS.128 and all ldmatrix tiles conflict-free.
// AT = float (x input) or __half (Y input). W always float.
// mode 0: f32 row-major out; 1: half scatter [b,h,s,d]; 2: scatter+RoPE.
// ---------------------------------------------------------------------------
#define BKH 32   // halves per K-tile

template <typename AT>
__global__ __launch_bounds__(256, 2)
void gemm_f16_kernel(const AT* __restrict__ A, const float* __restrict__ W,
                     void* __restrict__ out_v, int mode, const int* __restrict__ pos)
{
    __shared__ __align__(16) __half As[2][128 * BKH];
    __shared__ __align__(16) __half Bs[2][128 * BKH];

    const int tid  = threadIdx.x;
    const int lane = tid & 31;
    const int warp = tid >> 5;
    const int warpM = warp >> 1;     // 0..3
    const int warpN = warp & 1;      // 0..1
    const int bm = blockIdx.y * 128;
    const int bn = blockIdx.x * 128;

    // loader: thread -> rows lrow, lrow+64; halves [8*lc .. 8*lc+8)
    const int lrow = tid >> 2;       // 0..63
    const int lc   = tid & 3;        // chunk 0..3
    const int swz  = (lrow >> 1) & 3;
    const int st0 = (lrow * 4 + (lc ^ swz)) * 8;          // half index
    const int st1 = ((lrow + 64) * 4 + (lc ^ swz)) * 8;

    const AT*    Aptr = A + (size_t)(bm + lrow) * DM + 8 * lc;
    const float* Wptr = W + (size_t)(bn + lrow) * DM + 8 * lc;

    // staged global data
    float4 fa0a, fa0b, fa1a, fa1b;   // float-A path
    uint4  ha0, ha1;                 // half-A path
    float4 wb0a, wb0b, wb1a, wb1b;

    const unsigned int asm_base[2] = { smem_u32(As[0]), smem_u32(As[1]) };
    const unsigned int bsm_base[2] = { smem_u32(Bs[0]), smem_u32(Bs[1]) };

    const int b_rowl = ((lane >> 4) << 3) + (lane & 7);
    const int b_hi   = (lane >> 3) & 1;

    float4 acc[2][8];
#pragma unroll
    for (int mt = 0; mt < 2; mt++)
#pragma unroll
        for (int nt = 0; nt < 8; nt++) acc[mt][nt] = make_float4(0.f, 0.f, 0.f, 0.f);

    // prologue loads
    if constexpr (sizeof(AT) == 2) {
        ha0 = *(const uint4*)(Aptr);
        ha1 = *(const uint4*)(Aptr + (size_t)64 * DM);
    } else {
        fa0a = *(const float4*)(Aptr);      fa0b = *(const float4*)(Aptr + 4);
        fa1a = *(const float4*)(Aptr + (size_t)64 * DM);
        fa1b = *(const float4*)(Aptr + (size_t)64 * DM + 4);
    }
    wb0a = *(const float4*)(Wptr);      wb0b = *(const float4*)(Wptr + 4);
    wb1a = *(const float4*)(Wptr + (size_t)64 * DM);
    wb1b = *(const float4*)(Wptr + (size_t)64 * DM + 4);

    for (int kt = 0; kt < DM; kt += BKH) {
        const int buf = (kt >> 5) & 1;
        __half* as = As[buf];
        __half* bs = Bs[buf];
        if constexpr (sizeof(AT) == 2) {
            *(uint4*)&as[st0] = ha0;
            *(uint4*)&as[st1] = ha1;
        } else {
            __half2* d0 = (__half2*)&as[st0];
            d0[0] = __floats2half2_rn(fa0a.x, fa0a.y);
            d0[1] = __floats2half2_rn(fa0a.z, fa0a.w);
            d0[2] = __floats2half2_rn(fa0b.x, fa0b.y);
            d0[3] = __floats2half2_rn(fa0b.z, fa0b.w);
            __half2* d1 = (__half2*)&as[st1];
            d1[0] = __floats2half2_rn(fa1a.x, fa1a.y);
            d1[1] = __floats2half2_rn(fa1a.z, fa1a.w);
            d1[2] = __floats2half2_rn(fa1b.x, fa1b.y);
            d1[3] = __floats2half2_rn(fa1b.z, fa1b.w);
        }
        {
            __half2* d0 = (__half2*)&bs[st0];
            d0[0] = __floats2half2_rn(wb0a.x, wb0a.y);
            d0[1] = __floats2half2_rn(wb0a.z, wb0a.w);
            d0[2] = __floats2half2_rn(wb0b.x, wb0b.y);
            d0[3] = __floats2half2_rn(wb0b.z, wb0b.w);
            __half2* d1 = (__half2*)&bs[st1];
            d1[0] = __floats2half2_rn(wb1a.x, wb1a.y);
            d1[1] = __floats2half2_rn(wb1a.z, wb1a.w);
            d1[2] = __floats2half2_rn(wb1b.x, wb1b.y);
            d1[3] = __floats2half2_rn(wb1b.z, wb1b.w);
        }
        __syncthreads();

        if (kt + BKH < DM) {
            if constexpr (sizeof(AT) == 2) {
                ha0 = *(const uint4*)(Aptr + kt + BKH);
                ha1 = *(const uint4*)(Aptr + kt + BKH + (size_t)64 * DM);
            } else {
                fa0a = *(const float4*)(Aptr + kt + BKH);
                fa0b = *(const float4*)(Aptr + kt + BKH + 4);
                fa1a = *(const float4*)(Aptr + kt + BKH + (size_t)64 * DM);
                fa1b = *(const float4*)(Aptr + kt + BKH + (size_t)64 * DM + 4);
            }
            wb0a = *(const float4*)(Wptr + kt + BKH);
            wb0b = *(const float4*)(Wptr + kt + BKH + 4);
            wb1a = *(const float4*)(Wptr + kt + BKH + (size_t)64 * DM);
            wb1b = *(const float4*)(Wptr + kt + BKH + (size_t)64 * DM + 4);
        }

        const unsigned int ab = asm_base[buf];
        const unsigned int bb = bsm_base[buf];
#pragma unroll
        for (int s = 0; s < 2; s++) {      // k16 steps
            unsigned int af[2][4];
#pragma unroll
            for (int mt = 0; mt < 2; mt++) {
                const int row = warpM * 32 + mt * 16 + (lane & 15);
                const int c   = (2 * s + (lane >> 4)) ^ ((row >> 1) & 3);
                ldsm_x4(af[mt][0], af[mt][1], af[mt][2], af[mt][3],
                        ab + (unsigned)((row * 4 + c) << 4));
            }
#pragma unroll
            for (int p = 0; p < 4; p++) {
                const int row = warpN * 64 + 16 * p + b_rowl;
                const int c   = (2 * s + b_hi) ^ ((row >> 1) & 3);
                unsigned int r0, r1, r2, r3;
                ldsm_x4(r0, r1, r2, r3, bb + (unsigned)((row * 4 + c) << 4));
                mma_f16(acc[0][2 * p],     af[0], r0, r1);
                mma_f16(acc[1][2 * p],     af[1], r0, r1);
                mma_f16(acc[0][2 * p + 1], af[0], r2, r3);
                mma_f16(acc[1][2 * p + 1], af[1], r2, r3);
            }
        }
        __syncthreads();
    }

    const int fr = lane >> 2;
    const int fc = lane & 3;
    const bool is64 = (mode == 2) && (pos[1] == 0);
    float* fout = (float*)out_v;
    __half* hout = (__half*)out_v;
#pragma unroll
    for (int mt = 0; mt < 2; mt++) {
        const int gr0 = bm + warpM * 32 + mt * 16 + fr;
#pragma unroll
        for (int nt = 0; nt < 8; nt++) {
            const int gc = bn + warpN * 64 + nt * 8 + 2 * fc;
            float4 v = acc[mt][nt];
#pragma unroll
            for (int half_ = 0; half_ < 2; half_++) {
                const int grow = gr0 + half_ * 8;
                float e = half_ ? v.z : v.x;
                float o = half_ ? v.w : v.y;
                if (mode == 0) {
                    *(float2*)(fout + (size_t)grow * DM + gc) = make_float2(e, o);
                } else {
                    const int si = grow & (SEQ - 1), bi = grow >> 11;
                    const int head = gc >> 7, dd = gc & (DH - 1);
                    if (mode == 2) {
                        const int p = dd >> 1;
                        const int posv_i = is64 ? pos[2 * si] : pos[si];
                        const float inv_freq =
                            exp2f(-(float)p * (13.287712379549449f / 64.0f));
                        const float ang = (float)posv_i * inv_freq;
                        float sn, cs;
                        sincosf(ang, &sn, &cs);
                        const float e2 = e * cs - o * sn;
                        const float o2 = o * cs + e * sn;
                        e = e2; o = o2;
                    }
                    __half* dst = hout + ((((size_t)bi * NH + head) * SEQ + si) * DH + dd);
                    *(__half2*)dst = __floats2half2_rn(e, o);
                }
            }
        }
    }
}

// ---------------------------------------------------------------------------
// FP16 tensor-core causal flash attention (Br=128, Bc=64, d=128, 8 warps).
// mma.m16n8k16.f16. All fragments via ldmatrix b16 (V via .trans).
// Strides (16B chunks): Q/K/V 17, P 9  -> (row+chunk) mod 8 distinct ->
// conflict-free LDSM and STS. Smem 88 KB -> 2 CTAs/SM.
// ---------------------------------------------------------------------------
#define FQ_ST 17   // chunks per row (8 halves per chunk)
#define FP_ST 9
#define FL_Q_CH (128 * FQ_ST)
#define FL_K_CH (64 * FQ_ST)
#define FL_V_CH (64 * FQ_ST)
#define FL_P_CH (128 * FP_ST)
#define FL_BYTES ((FL_Q_CH + FL_K_CH + FL_V_CH + FL_P_CH) * 16)   // 88,064

__global__ __launch_bounds__(256)
void flash_f16_kernel(const __half* __restrict__ Q, const __half* __restrict__ K,
                      const __half* __restrict__ V, __half* __restrict__ Y)
{
    extern __shared__ __align__(16) __half smh[];
    __half* Qs = smh;
    __half* Ks = Qs + FL_Q_CH * 8;
    __half* Vs = Ks + FL_K_CH * 8;
    __half* Ps = Vs + FL_V_CH * 8;

    const int qb = blockIdx.x;           // 0..15 (128-row Q block)
    const int bh = blockIdx.y;           // 0..63
    const int b  = bh >> 4, h = bh & 15;
    const int tid  = threadIdx.x;
    const int warp = tid >> 5;
    const int lane = tid & 31;
    const int fr = lane >> 2;
    const int fc = lane & 3;

    const __half* Qb = Q + (size_t)bh * SEQ * DH;
    const __half* Kb = K + (size_t)bh * SEQ * DH;
    const __half* Vb = V + (size_t)bh * SEQ * DH;

    // load Q tile (128 x 128 halves = 128 rows x 16 chunks)
    for (int i = tid; i < 128 * 16; i += 256) {
        const int r = i >> 4, c = i & 15;
        *(uint4*)&Qs[(r * FQ_ST + c) << 3] =
            *(const uint4*)&Qb[(size_t)(qb * 128 + r) * DH + 8 * c];
    }

    float4 oacc[16];
#pragma unroll
    for (int nt = 0; nt < 16; nt++) oacc[nt] = make_float4(0.f, 0.f, 0.f, 0.f);
    float m0 = -1e30f, m1 = -1e30f, l0 = 0.f, l1 = 0.f;
    const float scale = 0.08838834764831845f;   // 1/sqrt(128)

    const int r0g = qb * 128 + 16 * warp + fr;
    const int r1g = r0g + 8;
    const int prow0 = (16 * warp + fr) * FP_ST * 8;   // half index
    const int prow1 = prow0 + 8 * FP_ST * 8;

    // ldmatrix bases (byte addresses)
    const int a_rowl = lane & 15;
    const unsigned int q_base = smem_u32(Qs) +
        (unsigned)((((16 * warp + a_rowl) * FQ_ST) + (lane >> 4)) << 4);
    const unsigned int p_base = smem_u32(Ps) +
        (unsigned)((((16 * warp + a_rowl) * FP_ST) + (lane >> 4)) << 4);
    const int b_rowl = ((lane >> 4) << 3) + (lane & 7);
    const int b_hi   = (lane >> 3) & 1;
    unsigned int k_base[4];
#pragma unroll
    for (int p = 0; p < 4; p++)
        k_base[p] = smem_u32(Ks) +
            (unsigned)((((16 * p + b_rowl) * FQ_ST) + b_hi) << 4);
    const unsigned int v_base = smem_u32(Vs) +
        (unsigned)(((a_rowl * FQ_ST) + (lane >> 4)) << 4);

    const int nj = 2 * qb + 2;
    for (int jb = 0; jb < nj; jb++) {
        __syncthreads();
        for (int i = tid; i < 64 * 16; i += 256) {
            const int r = i >> 4, c = i & 15;
            *(uint4*)&Ks[(r * FQ_ST + c) << 3] =
                *(const uint4*)&Kb[(size_t)(jb * 64 + r) * DH + 8 * c];
            *(uint4*)&Vs[(r * FQ_ST + c) << 3] =
                *(const uint4*)&Vb[(size_t)(jb * 64 + r) * DH + 8 * c];
        }
        __syncthreads();

        // ---- S = Q K^T  (warp tile 16 x 64), 8 k16 steps ----
        float4 sacc[8];
#pragma unroll
        for (int nt = 0; nt < 8; nt++) sacc[nt] = make_float4(0.f, 0.f, 0.f, 0.f);

#pragma unroll 4
        for (int ks = 0; ks < 8; ks++) {
            unsigned int af[4];
            ldsm_x4(af[0], af[1], af[2], af[3], q_base + 32u * ks);
#pragma unroll
            for (int p = 0; p < 4; p++) {
                unsigned int r0, r1, r2, r3;
                ldsm_x4(r0, r1, r2, r3, k_base[p] + 32u * ks);
                mma_f16(sacc[2 * p],     af, r0, r1);
                mma_f16(sacc[2 * p + 1], af, r2, r3);
            }
        }

        // ---- scale + causal mask ----
        const bool domask = (jb * 64 + 63) > (qb * 128 + 16 * warp);
#pragma unroll
        for (int nt = 0; nt < 8; nt++) {
            const int c0 = jb * 64 + 8 * nt + 2 * fc;
            const int c1 = c0 + 1;
            sacc[nt].x *= scale; sacc[nt].y *= scale;
            sacc[nt].z *= scale; sacc[nt].w *= scale;
            if (domask) {
                if (c0 > r0g) sacc[nt].x = -1e30f;
                if (c1 > r0g) sacc[nt].y = -1e30f;
                if (c0 > r1g) sacc[nt].z = -1e30f;
                if (c1 > r1g) sacc[nt].w = -1e30f;
            }
        }

        // ---- online softmax (rows fr, fr+8; quad reduction) ----
        float mx0 = -1e30f, mx1 = -1e30f;
#pragma unroll
        for (int nt = 0; nt < 8; nt++) {
            mx0 = fmaxf(mx0, fmaxf(sacc[nt].x, sacc[nt].y));
            mx1 = fmaxf(mx1, fmaxf(sacc[nt].z, sacc[nt].w));
        }
        mx0 = fmaxf(mx0, __shfl_xor_sync(0xffffffffu, mx0, 1));
        mx0 = fmaxf(mx0, __shfl_xor_sync(0xffffffffu, mx0, 2));
        mx1 = fmaxf(mx1, __shfl_xor_sync(0xffffffffu, mx1, 1));
        mx1 = fmaxf(mx1, __shfl_xor_sync(0xffffffffu, mx1, 2));

        const float mn0 = fmaxf(m0, mx0);
        const float mn1 = fmaxf(m1, mx1);
        const float alpha0 = __expf(m0 - mn0);
        const float alpha1 = __expf(m1 - mn1);
        m0 = mn0; m1 = mn1;

        float rs0 = 0.f, rs1 = 0.f;
#pragma unroll
        for (int nt = 0; nt < 8; nt++) {
            sacc[nt].x = __expf(sacc[nt].x - mn0);
            sacc[nt].y = __expf(sacc[nt].y - mn0);
            sacc[nt].z = __expf(sacc[nt].z - mn1);
            sacc[nt].w = __expf(sacc[nt].w - mn1);
            rs0 += sacc[nt].x + sacc[nt].y;
            rs1 += sacc[nt].z + sacc[nt].w;
        }
        rs0 += __shfl_xor_sync(0xffffffffu, rs0, 1);
        rs0 += __shfl_xor_sync(0xffffffffu, rs0, 2);
        rs1 += __shfl_xor_sync(0xffffffffu, rs1, 1);
        rs1 += __shfl_xor_sync(0xffffffffu, rs1, 2);
        l0 = l0 * alpha0 + rs0;
        l1 = l1 * alpha1 + rs1;

#pragma unroll
        for (int nt = 0; nt < 16; nt++) {
            oacc[nt].x *= alpha0; oacc[nt].y *= alpha0;
            oacc[nt].z *= alpha1; oacc[nt].w *= alpha1;
        }

        // ---- stage P as half (own warp rows only) ----
#pragma unroll
        for (int nt = 0; nt < 8; nt++) {
            const int cb = 8 * nt + 2 * fc;
            *(__half2*)&Ps[prow0 + cb] = __floats2half2_rn(sacc[nt].x, sacc[nt].y);
            *(__half2*)&Ps[prow1 + cb] = __floats2half2_rn(sacc[nt].z, sacc[nt].w);
        }
        __syncwarp();

        // ---- O += P V  (warp tile 16 x 128), 4 k16 steps ----
#pragma unroll
        for (int ks = 0; ks < 4; ks++) {
            unsigned int af[4];
            ldsm_x4(af[0], af[1], af[2], af[3], p_base + 32u * ks);
#pragma unroll
            for (int nc2 = 0; nc2 < 8; nc2++) {
                unsigned int r0, r1, r2, r3;
                ldsm_x4_trans(r0, r1, r2, r3,
                              v_base + (unsigned)(ks * 16 * FQ_ST * 16) + 32u * nc2);
                mma_f16(oacc[2 * nc2],     af, r0, r1);
                mma_f16(oacc[2 * nc2 + 1], af, r2, r3);
            }
        }
        __syncwarp();   // P reads done before next iteration overwrites
    }

    // ---- epilogue: normalize, write half Y [b, s, h*128+d] ----
    const float inv0 = 1.0f / l0;
    const float inv1 = 1.0f / l1;
    const size_t y0 = ((size_t)(b * SEQ + r0g)) * DM + h * DH;
    const size_t y1 = ((size_t)(b * SEQ + r1g)) * DM + h * DH;
#pragma unroll
    for (int nt = 0; nt < 16; nt++) {
        const int cb = 8 * nt + 2 * fc;
        *(__half2*)&Y[y0 + cb] = __floats2half2_rn(oacc[nt].x * inv0, oacc[nt].y * inv0);
        *(__half2*)&Y[y1 + cb] = __floats2half2_rn(oacc[nt].z * inv1, oacc[nt].w * inv1);
    }
}

// ---------------------------------------------------------------------------
extern "C" void kernel_launch(void* const* d_in, const int* in_sizes, int n_in,
                              void* d_out, int out_size)
{
    (void)in_sizes; (void)n_in; (void)out_size;
    const float* x   = (const float*)d_in[0];
    const int*   pos = (const int*)d_in[1];   // int32 or int64: detected in-kernel
    const float* Wq  = (const float*)d_in[2];
    const float* Wk  = (const float*)d_in[3];
    const float* Wv  = (const float*)d_in[4];
    const float* Wo  = (const float*)d_in[5];
    float* out = (float*)d_out;

    __half *Qp, *Kp, *Vp, *Yp;
    cudaGetSymbolAddress((void**)&Qp, g_Q);
    cudaGetSymbolAddress((void**)&Kp, g_K);
    cudaGetSymbolAddress((void**)&Vp, g_V);
    cudaGetSymbolAddress((void**)&Yp, g_Y);

    dim3 ggrid(DM / 128, M_TOTAL / 128);   // (16, 64)
    gemm_f16_kernel<float><<<ggrid, 256>>>(x, Wq, Qp, 2, pos);  // + fused RoPE
    gemm_f16_kernel<float><<<ggrid, 256>>>(x, Wk, Kp, 2, pos);  // + fused RoPE
    gemm_f16_kernel<float><<<ggrid, 256>>>(x, Wv, Vp, 1, pos);

    cudaFuncSetAttribute(flash_f16_kernel,
                         cudaFuncAttributeMaxDynamicSharedMemorySize, FL_BYTES);
    flash_f16_kernel<<<dim3(SEQ / 128, BHEADS), 256, FL_BYTES>>>(Qp, Kp, Vp, Yp);

    gemm_f16_kernel<__half><<<ggrid, 256>>>(Yp, Wo, out, 0, pos);
}

// round 13
// speedup vs baseline: 5.4584x; 1.1005x over previous
#include <cuda_runtime.h>
#include <cuda_fp16.h>
#include <stdint.h>
#include <math.h>

#define DM   2048
#define NH   16
#define DH   128
#define SEQ  2048
#define BATCH 4
#define M_TOTAL (BATCH * SEQ)   // 8192
#define BHEADS  (BATCH * NH)    // 64

// Scratch (allocations forbidden; __device__ globals are the sanctioned path)
__device__ __half g_Q[BHEADS * SEQ * DH];   // [b,h,s,d]
__device__ __half g_K[BHEADS * SEQ * DH];
__device__ __half g_V[BHEADS * SEQ * DH];
__device__ __half g_Y[M_TOTAL * DM];        // [b,s,h*d]

__device__ __forceinline__ void mma_f16(float4& d, const unsigned int a[4],
                                        unsigned int b0, unsigned int b1) {
    asm volatile(
        "mma.sync.aligned.m16n8k16.row.col.f32.f16.f16.f32 "
        "{%0,%1,%2,%3}, {%4,%5,%6,%7}, {%8,%9}, {%0,%1,%2,%3};"
        : "+f"(d.x), "+f"(d.y), "+f"(d.z), "+f"(d.w)
        : "r"(a[0]), "r"(a[1]), "r"(a[2]), "r"(a[3]), "r"(b0), "r"(b1));
}

__device__ __forceinline__ void ldsm_x4(unsigned int& r0, unsigned int& r1,
                                        unsigned int& r2, unsigned int& r3,
                                        unsigned int addr) {
    asm volatile("ldmatrix.sync.aligned.m8n8.x4.shared.b16 {%0,%1,%2,%3}, [%4];"
                 : "=r"(r0), "=r"(r1), "=r"(r2), "=r"(r3) : "r"(addr));
}

__device__ __forceinline__ void ldsm_x4_trans(unsigned int& r0, unsigned int& r1,
                                              unsigned int& r2, unsigned int& r3,
                                              unsigned int addr) {
    asm volatile("ldmatrix.sync.aligned.m8n8.x4.trans.shared.b16 {%0,%1,%2,%3}, [%4];"
                 : "=r"(r0), "=r"(r1), "=r"(r2), "=r"(r3) : "r"(addr));
}

__device__ __forceinline__ unsigned int smem_u32(const void* p) {
    return (unsigned int)__cvta_generic_to_shared(p);
}

// ---------------------------------------------------------------------------
// FP16 tensor-core NT GEMM: C[M,N] = A[M,K] * W[N,K]^T  (M=8192, N=K=2048)
// Block 128x128, BK=32 halves, 256 threads (8 warps 4Mx2N), warp tile 32x64,
// mma.m16n8k16.f16 with f32 accum. Smem [row][32 halves], 16B-chunk swizzle
// c^((row>>1)&3): STS.128 and all ldmatrix tiles conflict-free.
// AT = float (x input) or __half (Y input). W always float.
// mode 0: f32 row-major out; 1: half scatter [b,h,s,d]; 2: scatter+RoPE.
// ---------------------------------------------------------------------------
#define BKH 32   // halves per K-tile

template <typename AT>
__global__ __launch_bounds__(256, 2)
void gemm_f16_kernel(const AT* __restrict__ A, const float* __restrict__ W,
                     void* __restrict__ out_v, int mode, const int* __restrict__ pos)
{
    __shared__ __align__(16) __half As[2][128 * BKH];
    __shared__ __align__(16) __half Bs[2][128 * BKH];

    const int tid  = threadIdx.x;
    const int lane = tid & 31;
    const int warp = tid >> 5;
    const int warpM = warp >> 1;     // 0..3
    const int warpN = warp & 1;      // 0..1
    const int bm = blockIdx.y * 128;
    const int bn = blockIdx.x * 128;

    // loader: thread -> rows lrow, lrow+64; halves [8*lc .. 8*lc+8)
    const int lrow = tid >> 2;       // 0..63
    const int lc   = tid & 3;        // chunk 0..3
    const int swz  = (lrow >> 1) & 3;
    const int st0 = (lrow * 4 + (lc ^ swz)) * 8;          // half index
    const int st1 = ((lrow + 64) * 4 + (lc ^ swz)) * 8;

    const AT*    Aptr = A + (size_t)(bm + lrow) * DM + 8 * lc;
    const float* Wptr = W + (size_t)(bn + lrow) * DM + 8 * lc;

    // staged global data
    float4 fa0a, fa0b, fa1a, fa1b;   // float-A path
    uint4  ha0, ha1;                 // half-A path
    float4 wb0a, wb0b, wb1a, wb1b;

    const unsigned int asm_base[2] = { smem_u32(As[0]), smem_u32(As[1]) };
    const unsigned int bsm_base[2] = { smem_u32(Bs[0]), smem_u32(Bs[1]) };

    const int b_rowl = ((lane >> 4) << 3) + (lane & 7);
    const int b_hi   = (lane >> 3) & 1;

    float4 acc[2][8];
#pragma unroll
    for (int mt = 0; mt < 2; mt++)
#pragma unroll
        for (int nt = 0; nt < 8; nt++) acc[mt][nt] = make_float4(0.f, 0.f, 0.f, 0.f);

    // prologue loads
    if constexpr (sizeof(AT) == 2) {
        ha0 = *(const uint4*)(Aptr);
        ha1 = *(const uint4*)(Aptr + (size_t)64 * DM);
    } else {
        fa0a = *(const float4*)(Aptr);      fa0b = *(const float4*)(Aptr + 4);
        fa1a = *(const float4*)(Aptr + (size_t)64 * DM);
        fa1b = *(const float4*)(Aptr + (size_t)64 * DM + 4);
    }
    wb0a = *(const float4*)(Wptr);      wb0b = *(const float4*)(Wptr + 4);
    wb1a = *(const float4*)(Wptr + (size_t)64 * DM);
    wb1b = *(const float4*)(Wptr + (size_t)64 * DM + 4);

    for (int kt = 0; kt < DM; kt += BKH) {
        const int buf = (kt >> 5) & 1;
        __half* as = As[buf];
        __half* bs = Bs[buf];
        if constexpr (sizeof(AT) == 2) {
            *(uint4*)&as[st0] = ha0;
            *(uint4*)&as[st1] = ha1;
        } else {
            __half2* d0 = (__half2*)&as[st0];
            d0[0] = __floats2half2_rn(fa0a.x, fa0a.y);
            d0[1] = __floats2half2_rn(fa0a.z, fa0a.w);
            d0[2] = __floats2half2_rn(fa0b.x, fa0b.y);
            d0[3] = __floats2half2_rn(fa0b.z, fa0b.w);
            __half2* d1 = (__half2*)&as[st1];
            d1[0] = __floats2half2_rn(fa1a.x, fa1a.y);
            d1[1] = __floats2half2_rn(fa1a.z, fa1a.w);
            d1[2] = __floats2half2_rn(fa1b.x, fa1b.y);
            d1[3] = __floats2half2_rn(fa1b.z, fa1b.w);
        }
        {
            __half2* d0 = (__half2*)&bs[st0];
            d0[0] = __floats2half2_rn(wb0a.x, wb0a.y);
            d0[1] = __floats2half2_rn(wb0a.z, wb0a.w);
            d0[2] = __floats2half2_rn(wb0b.x, wb0b.y);
            d0[3] = __floats2half2_rn(wb0b.z, wb0b.w);
            __half2* d1 = (__half2*)&bs[st1];
            d1[0] = __floats2half2_rn(wb1a.x, wb1a.y);
            d1[1] = __floats2half2_rn(wb1a.z, wb1a.w);
            d1[2] = __floats2half2_rn(wb1b.x, wb1b.y);
            d1[3] = __floats2half2_rn(wb1b.z, wb1b.w);
        }
        __syncthreads();

        if (kt + BKH < DM) {
            if constexpr (sizeof(AT) == 2) {
                ha0 = *(const uint4*)(Aptr + kt + BKH);
                ha1 = *(const uint4*)(Aptr + kt + BKH + (size_t)64 * DM);
            } else {
                fa0a = *(const float4*)(Aptr + kt + BKH);
                fa0b = *(const float4*)(Aptr + kt + BKH + 4);
                fa1a = *(const float4*)(Aptr + kt + BKH + (size_t)64 * DM);
                fa1b = *(const float4*)(Aptr + kt + BKH + (size_t)64 * DM + 4);
            }
            wb0a = *(const float4*)(Wptr + kt + BKH);
            wb0b = *(const float4*)(Wptr + kt + BKH + 4);
            wb1a = *(const float4*)(Wptr + kt + BKH + (size_t)64 * DM);
            wb1b = *(const float4*)(Wptr + kt + BKH + (size_t)64 * DM + 4);
        }

        const unsigned int ab = asm_base[buf];
        const unsigned int bb = bsm_base[buf];
#pragma unroll
        for (int s = 0; s < 2; s++) {      // k16 steps
            unsigned int af[2][4];
#pragma unroll
            for (int mt = 0; mt < 2; mt++) {
                const int row = warpM * 32 + mt * 16 + (lane & 15);
                const int c   = (2 * s + (lane >> 4)) ^ ((row >> 1) & 3);
                ldsm_x4(af[mt][0], af[mt][1], af[mt][2], af[mt][3],
                        ab + (unsigned)((row * 4 + c) << 4));
            }
#pragma unroll
            for (int p = 0; p < 4; p++) {
                const int row = warpN * 64 + 16 * p + b_rowl;
                const int c   = (2 * s + b_hi) ^ ((row >> 1) & 3);
                unsigned int r0, r1, r2, r3;
                ldsm_x4(r0, r1, r2, r3, bb + (unsigned)((row * 4 + c) << 4));
                mma_f16(acc[0][2 * p],     af[0], r0, r1);
                mma_f16(acc[1][2 * p],     af[1], r0, r1);
                mma_f16(acc[0][2 * p + 1], af[0], r2, r3);
                mma_f16(acc[1][2 * p + 1], af[1], r2, r3);
            }
        }
        __syncthreads();
    }

    const int fr = lane >> 2;
    const int fc = lane & 3;
    const bool is64 = (mode == 2) && (pos[1] == 0);
    float* fout = (float*)out_v;
    __half* hout = (__half*)out_v;
#pragma unroll
    for (int mt = 0; mt < 2; mt++) {
        const int gr0 = bm + warpM * 32 + mt * 16 + fr;
#pragma unroll
        for (int nt = 0; nt < 8; nt++) {
            const int gc = bn + warpN * 64 + nt * 8 + 2 * fc;
            float4 v = acc[mt][nt];
#pragma unroll
            for (int half_ = 0; half_ < 2; half_++) {
                const int grow = gr0 + half_ * 8;
                float e = half_ ? v.z : v.x;
                float o = half_ ? v.w : v.y;
                if (mode == 0) {
                    *(float2*)(fout + (size_t)grow * DM + gc) = make_float2(e, o);
                } else {
                    const int si = grow & (SEQ - 1), bi = grow >> 11;
                    const int head = gc >> 7, dd = gc & (DH - 1);
                    if (mode == 2) {
                        const int p = dd >> 1;
                        const int posv_i = is64 ? pos[2 * si] : pos[si];
                        const float inv_freq =
                            exp2f(-(float)p * (13.287712379549449f / 64.0f));
                        const float ang = (float)posv_i * inv_freq;
                        float sn, cs;
                        sincosf(ang, &sn, &cs);
                        const float e2 = e * cs - o * sn;
                        const float o2 = o * cs + e * sn;
                        e = e2; o = o2;
                    }
                    __half* dst = hout + ((((size_t)bi * NH + head) * SEQ + si) * DH + dd);
                    *(__half2*)dst = __floats2half2_rn(e, o);
                }
            }
        }
    }
}

// ---------------------------------------------------------------------------
// FP16 tensor-core causal flash attention (Br=128, Bc=64, d=128, 8 warps).
// mma.m16n8k16.f16. All fragments via ldmatrix b16 (V via .trans).
// Strides (16B chunks): Q/K/V 17, P 9  -> (row+chunk) mod 8 distinct ->
// conflict-free LDSM and STS. Smem 88 KB; __launch_bounds__(256,2) caps regs
// at 128 so the second CTA per SM is register-feasible (was 138 regs -> occ
// 12.5%). Heavy tiles (large qb) launch first to pack the tail wave.
// ---------------------------------------------------------------------------
#define FQ_ST 17   // chunks per row (8 halves per chunk)
#define FP_ST 9
#define FL_Q_CH (128 * FQ_ST)
#define FL_K_CH (64 * FQ_ST)
#define FL_V_CH (64 * FQ_ST)
#define FL_P_CH (128 * FP_ST)
#define FL_BYTES ((FL_Q_CH + FL_K_CH + FL_V_CH + FL_P_CH) * 16)   // 88,064

__global__ __launch_bounds__(256, 2)
void flash_f16_kernel(const __half* __restrict__ Q, const __half* __restrict__ K,
                      const __half* __restrict__ V, __half* __restrict__ Y)
{
    extern __shared__ __align__(16) __half smh[];
    __half* Qs = smh;
    __half* Ks = Qs + FL_Q_CH * 8;
    __half* Vs = Ks + FL_K_CH * 8;
    __half* Ps = Vs + FL_V_CH * 8;

    const int qb = (gridDim.x - 1) - blockIdx.x;  // heavy tiles first
    const int bh = blockIdx.y;           // 0..63
    const int b  = bh >> 4, h = bh & 15;
    const int tid  = threadIdx.x;
    const int warp = tid >> 5;
    const int lane = tid & 31;
    const int fr = lane >> 2;
    const int fc = lane & 3;

    const __half* Qb = Q + (size_t)bh * SEQ * DH;
    const __half* Kb = K + (size_t)bh * SEQ * DH;
    const __half* Vb = V + (size_t)bh * SEQ * DH;

    // load Q tile (128 x 128 halves = 128 rows x 16 chunks)
    for (int i = tid; i < 128 * 16; i += 256) {
        const int r = i >> 4, c = i & 15;
        *(uint4*)&Qs[(r * FQ_ST + c) << 3] =
            *(const uint4*)&Qb[(size_t)(qb * 128 + r) * DH + 8 * c];
    }

    float4 oacc[16];
#pragma unroll
    for (int nt = 0; nt < 16; nt++) oacc[nt] = make_float4(0.f, 0.f, 0.f, 0.f);
    float m0 = -1e30f, m1 = -1e30f, l0 = 0.f, l1 = 0.f;
    const float scale = 0.08838834764831845f;   // 1/sqrt(128)

    const int r0g = qb * 128 + 16 * warp + fr;
    const int r1g = r0g + 8;
    const int prow0 = (16 * warp + fr) * FP_ST * 8;   // half index
    const int prow1 = prow0 + 8 * FP_ST * 8;

    // ldmatrix bases (byte addresses)
    const int a_rowl = lane & 15;
    const unsigned int q_base = smem_u32(Qs) +
        (unsigned)((((16 * warp + a_rowl) * FQ_ST) + (lane >> 4)) << 4);
    const unsigned int p_base = smem_u32(Ps) +
        (unsigned)((((16 * warp + a_rowl) * FP_ST) + (lane >> 4)) << 4);
    const int b_rowl = ((lane >> 4) << 3) + (lane & 7);
    const int b_hi   = (lane >> 3) & 1;
    unsigned int k_base[4];
#pragma unroll
    for (int p = 0; p < 4; p++)
        k_base[p] = smem_u32(Ks) +
            (unsigned)((((16 * p + b_rowl) * FQ_ST) + b_hi) << 4);
    const unsigned int v_base = smem_u32(Vs) +
        (unsigned)(((a_rowl * FQ_ST) + (lane >> 4)) << 4);

    const int nj = 2 * qb + 2;
    for (int jb = 0; jb < nj; jb++) {
        __syncthreads();
        for (int i = tid; i < 64 * 16; i += 256) {
            const int r = i >> 4, c = i & 15;
            *(uint4*)&Ks[(r * FQ_ST + c) << 3] =
                *(const uint4*)&Kb[(size_t)(jb * 64 + r) * DH + 8 * c];
            *(uint4*)&Vs[(r * FQ_ST + c) << 3] =
                *(const uint4*)&Vb[(size_t)(jb * 64 + r) * DH + 8 * c];
        }
        __syncthreads();

        // ---- S = Q K^T  (warp tile 16 x 64), 8 k16 steps ----
        float4 sacc[8];
#pragma unroll
        for (int nt = 0; nt < 8; nt++) sacc[nt] = make_float4(0.f, 0.f, 0.f, 0.f);

#pragma unroll 4
        for (int ks = 0; ks < 8; ks++) {
            unsigned int af[4];
            ldsm_x4(af[0], af[1], af[2], af[3], q_base + 32u * ks);
#pragma unroll
            for (int p = 0; p < 4; p++) {
                unsigned int r0, r1, r2, r3;
                ldsm_x4(r0, r1, r2, r3, k_base[p] + 32u * ks);
                mma_f16(sacc[2 * p],     af, r0, r1);
                mma_f16(sacc[2 * p + 1], af, r2, r3);
            }
        }

        // ---- scale + causal mask ----
        const bool domask = (jb * 64 + 63) > (qb * 128 + 16 * warp);
#pragma unroll
        for (int nt = 0; nt < 8; nt++) {
            const int c0 = jb * 64 + 8 * nt + 2 * fc;
            const int c1 = c0 + 1;
            sacc[nt].x *= scale; sacc[nt].y *= scale;
            sacc[nt].z *= scale; sacc[nt].w *= scale;
            if (domask) {
                if (c0 > r0g) sacc[nt].x = -1e30f;
                if (c1 > r0g) sacc[nt].y = -1e30f;
                if (c0 > r1g) sacc[nt].z = -1e30f;
                if (c1 > r1g) sacc[nt].w = -1e30f;
            }
        }

        // ---- online softmax (rows fr, fr+8; quad reduction) ----
        float mx0 = -1e30f, mx1 = -1e30f;
#pragma unroll
        for (int nt = 0; nt < 8; nt++) {
            mx0 = fmaxf(mx0, fmaxf(sacc[nt].x, sacc[nt].y));
            mx1 = fmaxf(mx1, fmaxf(sacc[nt].z, sacc[nt].w));
        }
        mx0 = fmaxf(mx0, __shfl_xor_sync(0xffffffffu, mx0, 1));
        mx0 = fmaxf(mx0, __shfl_xor_sync(0xffffffffu, mx0, 2));
        mx1 = fmaxf(mx1, __shfl_xor_sync(0xffffffffu, mx1, 1));
        mx1 = fmaxf(mx1, __shfl_xor_sync(0xffffffffu, mx1, 2));

        const float mn0 = fmaxf(m0, mx0);
        const float mn1 = fmaxf(m1, mx1);
        const float alpha0 = __expf(m0 - mn0);
        const float alpha1 = __expf(m1 - mn1);
        m0 = mn0; m1 = mn1;

        float rs0 = 0.f, rs1 = 0.f;
#pragma unroll
        for (int nt = 0; nt < 8; nt++) {
            sacc[nt].x = __expf(sacc[nt].x - mn0);
            sacc[nt].y = __expf(sacc[nt].y - mn0);
            sacc[nt].z = __expf(sacc[nt].z - mn1);
            sacc[nt].w = __expf(sacc[nt].w - mn1);
            rs0 += sacc[nt].x + sacc[nt].y;
            rs1 += sacc[nt].z + sacc[nt].w;
        }
        rs0 += __shfl_xor_sync(0xffffffffu, rs0, 1);
        rs0 += __shfl_xor_sync(0xffffffffu, rs0, 2);
        rs1 += __shfl_xor_sync(0xffffffffu, rs1, 1);
        rs1 += __shfl_xor_sync(0xffffffffu, rs1, 2);
        l0 = l0 * alpha0 + rs0;
        l1 = l1 * alpha1 + rs1;

#pragma unroll
        for (int nt = 0; nt < 16; nt++) {
            oacc[nt].x *= alpha0; oacc[nt].y *= alpha0;
            oacc[nt].z *= alpha1; oacc[nt].w *= alpha1;
        }

        // ---- stage P as half (own warp rows only) ----
#pragma unroll
        for (int nt = 0; nt < 8; nt++) {
            const int cb = 8 * nt + 2 * fc;
            *(__half2*)&Ps[prow0 + cb] = __floats2half2_rn(sacc[nt].x, sacc[nt].y);
            *(__half2*)&Ps[prow1 + cb] = __floats2half2_rn(sacc[nt].z, sacc[nt].w);
        }
        __syncwarp();

        // ---- O += P V  (warp tile 16 x 128), 4 k16 steps ----
#pragma unroll
        for (int ks = 0; ks < 4; ks++) {
            unsigned int af[4];
            ldsm_x4(af[0], af[1], af[2], af[3], p_base + 32u * ks);
#pragma unroll
            for (int nc2 = 0; nc2 < 8; nc2++) {
                unsigned int r0, r1, r2, r3;
                ldsm_x4_trans(r0, r1, r2, r3,
                              v_base + (unsigned)(ks * 16 * FQ_ST * 16) + 32u * nc2);
                mma_f16(oacc[2 * nc2],     af, r0, r1);
                mma_f16(oacc[2 * nc2 + 1], af, r2, r3);
            }
        }
        __syncwarp();   // P reads done before next iteration overwrites
    }

    // ---- epilogue: normalize, write half Y [b, s, h*128+d] ----
    const float inv0 = 1.0f / l0;
    const float inv1 = 1.0f / l1;
    const size_t y0 = ((size_t)(b * SEQ + r0g)) * DM + h * DH;
    const size_t y1 = ((size_t)(b * SEQ + r1g)) * DM + h * DH;
#pragma unroll
    for (int nt = 0; nt < 16; nt++) {
        const int cb = 8 * nt + 2 * fc;
        *(__half2*)&Y[y0 + cb] = __floats2half2_rn(oacc[nt].x * inv0, oacc[nt].y * inv0);
        *(__half2*)&Y[y1 + cb] = __floats2half2_rn(oacc[nt].z * inv1, oacc[nt].w * inv1);
    }
}

// ---------------------------------------------------------------------------
extern "C" void kernel_launch(void* const* d_in, const int* in_sizes, int n_in,
                              void* d_out, int out_size)
{
    (void)in_sizes; (void)n_in; (void)out_size;
    const float* x   = (const float*)d_in[0];
    const int*   pos = (const int*)d_in[1];   // int32 or int64: detected in-kernel
    const float* Wq  = (const float*)d_in[2];
    const float* Wk  = (const float*)d_in[3];
    const float* Wv  = (const float*)d_in[4];
    const float* Wo  = (const float*)d_in[5];
    float* out = (float*)d_out;

    __half *Qp, *Kp, *Vp, *Yp;
    cudaGetSymbolAddress((void**)&Qp, g_Q);
    cudaGetSymbolAddress((void**)&Kp, g_K);
    cudaGetSymbolAddress((void**)&Vp, g_V);
    cudaGetSymbolAddress((void**)&Yp, g_Y);

    dim3 ggrid(DM / 128, M_TOTAL / 128);   // (16, 64)
    gemm_f16_kernel<float><<<ggrid, 256>>>(x, Wq, Qp, 2, pos);  // + fused RoPE
    gemm_f16_kernel<float><<<ggrid, 256>>>(x, Wk, Kp, 2, pos);  // + fused RoPE
    gemm_f16_kernel<float><<<ggrid, 256>>>(x, Wv, Vp, 1, pos);

    cudaFuncSetAttribute(flash_f16_kernel,
                         cudaFuncAttributeMaxDynamicSharedMemorySize, FL_BYTES);
    flash_f16_kernel<<<dim3(SEQ / 128, BHEADS), 256, FL_BYTES>>>(Qp, Kp, Vp, Yp);

    gemm_f16_kernel<__half><<<ggrid, 256>>>(Yp, Wo, out, 0, pos);
}

// round 17
// speedup vs baseline: 7.1848x; 1.3163x over previous
#include <cuda_runtime.h>
#include <cuda_fp16.h>
#include <stdint.h>
#include <math.h>

#define DM   2048
#define NH   16
#define DH   128
#define SEQ  2048
#define BATCH 4
#define M_TOTAL (BATCH * SEQ)   // 8192
#define BHEADS  (BATCH * NH)    // 64

// Scratch (allocations forbidden; __device__ globals are the sanctioned path)
__device__ __half g_Q[BHEADS * SEQ * DH];   // [b,h,s,d]
__device__ __half g_K[BHEADS * SEQ * DH];
__device__ __half g_V[BHEADS * SEQ * DH];
__device__ __half g_Y[M_TOTAL * DM];        // [b,s,h*d]
__device__ __half g_xh[M_TOTAL * DM];       // x in fp16
__device__ __half g_Wqh[DM * DM];
__device__ __half g_Wkh[DM * DM];
__device__ __half g_Wvh[DM * DM];
__device__ __half g_Woh[DM * DM];

// ---------------------------------------------------------------------------
// helpers
// ---------------------------------------------------------------------------
__device__ __forceinline__ unsigned int smem_u32(const void* p) {
    return (unsigned int)__cvta_generic_to_shared(p);
}

__device__ __forceinline__ void mma_f16(float4& d, const unsigned int a[4],
                                        unsigned int b0, unsigned int b1) {
    asm volatile(
        "mma.sync.aligned.m16n8k16.row.col.f32.f16.f16.f32 "
        "{%0,%1,%2,%3}, {%4,%5,%6,%7}, {%8,%9}, {%0,%1,%2,%3};"
        : "+f"(d.x), "+f"(d.y), "+f"(d.z), "+f"(d.w)
        : "r"(a[0]), "r"(a[1]), "r"(a[2]), "r"(a[3]), "r"(b0), "r"(b1));
}
__device__ __forceinline__ void ldsm_x4(unsigned int& r0, unsigned int& r1,
                                        unsigned int& r2, unsigned int& r3,
                                        unsigned int addr) {
    asm volatile("ldmatrix.sync.aligned.m8n8.x4.shared.b16 {%0,%1,%2,%3}, [%4];"
                 : "=r"(r0), "=r"(r1), "=r"(r2), "=r"(r3) : "r"(addr));
}
__device__ __forceinline__ void ldsm_x4_trans(unsigned int& r0, unsigned int& r1,
                                              unsigned int& r2, unsigned int& r3,
                                              unsigned int addr) {
    asm volatile("ldmatrix.sync.aligned.m8n8.x4.trans.shared.b16 {%0,%1,%2,%3}, [%4];"
                 : "=r"(r0), "=r"(r1), "=r"(r2), "=r"(r3) : "r"(addr));
}
__device__ __forceinline__ void cp_async16(unsigned int dst, const void* src) {
    asm volatile("cp.async.ca.shared.global [%0], [%1], 16;"
                 :: "r"(dst), "l"(src) : "memory");
}
#define CP_COMMIT() asm volatile("cp.async.commit_group;" ::: "memory")
#define CP_WAIT(n)  asm volatile("cp.async.wait_group %0;" :: "n"(n) : "memory")

__device__ __forceinline__ unsigned int pack_h2(float a, float b) {
    __half2 h = __floats2half2_rn(a, b);
    return *(unsigned int*)&h;
}

// ---------------------------------------------------------------------------
// fp32 -> fp16 conversion (grid-stride, float4 granularity)
// ---------------------------------------------------------------------------
__global__ void f2h_kernel(const float* __restrict__ in, __half* __restrict__ out, int n4)
{
    for (int i = blockIdx.x * blockDim.x + threadIdx.x; i < n4; i += gridDim.x * blockDim.x) {
        float4 v = ((const float4*)in)[i];
        __half2 h0 = __floats2half2_rn(v.x, v.y);
        __half2 h1 = __floats2half2_rn(v.z, v.w);
        ((uint2*)out)[i] = make_uint2(*(unsigned int*)&h0, *(unsigned int*)&h1);
    }
}

// ---------------------------------------------------------------------------
// FP16 NT GEMM with 4-stage cp.async pipeline.
// C[M,N] = A[M,K] * B[N,K]^T, A and B fp16 K-major. Block 128x128, BK=32
// halves, 256 threads (8 warps 4Mx2N), warp tile 32x64, mma.m16n8k16.
// Smem per stage per matrix: 128 rows x 32 halves (64B/row), 16B-chunk XOR
// swizzle pos = row*4 + (c ^ ((row>>1)&3)) -> cp.async(16B) and all ldmatrix
// tiles conflict-free. 4 stages x 2 matrices x 8KB = 64KB dynamic smem.
// mode 0: f32 row-major out; 1: half scatter [b,h,s,d]; 2: scatter+RoPE.
// ---------------------------------------------------------------------------
#define BKH    32                 // halves per K-chunk
#define NSTAGE 4
#define NIT    (DM / BKH)         // 64
#define STG_B  (128 * BKH * 2)    // bytes per stage per matrix = 8192
#define GS_TOTAL (2 * NSTAGE * STG_B)   // 65536

__global__ __launch_bounds__(256, 2)
void gemm_f16_cp(const __half* __restrict__ A, const __half* __restrict__ B,
                 void* __restrict__ out_v, int mode, const int* __restrict__ pos)
{
    extern __shared__ __align__(16) __half gsm[];
    __half* As = gsm;                                  // NSTAGE stages
    __half* Bs = gsm + NSTAGE * (STG_B / 2);

    const int tid  = threadIdx.x;
    const int lane = tid & 31;
    const int warp = tid >> 5;
    const int warpM = warp >> 1;     // 0..3
    const int warpN = warp & 1;      // 0..1
    const int bm = blockIdx.y * 128;
    const int bn = blockIdx.x * 128;

    // loader: thread -> row tid>>1 (0..127), chunk pair (tid&1)*2 + {0,1}
    const int lr   = tid >> 1;
    const int hsel = tid & 1;
    const __half* Ap = A + (size_t)(bm + lr) * DM + hsel * 16;
    const __half* Bp = B + (size_t)(bn + lr) * DM + hsel * 16;
    unsigned int a_dst[2], b_dst[2];
#pragma unroll
    for (int j = 0; j < 2; j++) {
        const int c = hsel * 2 + j;
        const int p = lr * 4 + (c ^ ((lr >> 1) & 3));
        a_dst[j] = smem_u32(As) + (unsigned)(p << 4);
        b_dst[j] = smem_u32(Bs) + (unsigned)(p << 4);
    }

    const int b_rowl = ((lane >> 4) << 3) + (lane & 7);
    const int b_hi   = (lane >> 3) & 1;

    float4 acc[2][8];
#pragma unroll
    for (int mt = 0; mt < 2; mt++)
#pragma unroll
        for (int nt = 0; nt < 8; nt++) acc[mt][nt] = make_float4(0.f, 0.f, 0.f, 0.f);

    // prologue: issue stages 0..NSTAGE-2
#pragma unroll
    for (int s = 0; s < NSTAGE - 1; s++) {
        const unsigned so = (unsigned)(s * STG_B);
        const int kt = s * BKH;
        cp_async16(a_dst[0] + so, Ap + kt);
        cp_async16(a_dst[1] + so, Ap + kt + 8);
        cp_async16(b_dst[0] + so, Bp + kt);
        cp_async16(b_dst[1] + so, Bp + kt + 8);
        CP_COMMIT();
    }

    const unsigned int as0 = smem_u32(As);
    const unsigned int bs0 = smem_u32(Bs);

    for (int i = 0; i < NIT; i++) {
        CP_WAIT(NSTAGE - 2);          // stage i landed
        __syncthreads();              // visible to all warps; prev compute done

        // issue stage i+NSTAGE-1 (into the buffer freed by compute(i-1))
        if (i + NSTAGE - 1 < NIT) {
            const unsigned so = (unsigned)(((i + NSTAGE - 1) % NSTAGE) * STG_B);
            const int kt = (i + NSTAGE - 1) * BKH;
            cp_async16(a_dst[0] + so, Ap + kt);
            cp_async16(a_dst[1] + so, Ap + kt + 8);
            cp_async16(b_dst[0] + so, Bp + kt);
            cp_async16(b_dst[1] + so, Bp + kt + 8);
        }
        CP_COMMIT();                  // unconditional: keeps group count in step

        const unsigned int ab = as0 + (unsigned)((i % NSTAGE) * STG_B);
        const unsigned int bb = bs0 + (unsigned)((i % NSTAGE) * STG_B);
#pragma unroll
        for (int s = 0; s < 2; s++) {      // two k16 steps
            unsigned int af[2][4];
#pragma unroll
            for (int mt = 0; mt < 2; mt++) {
                const int row = warpM * 32 + mt * 16 + (lane & 15);
                const int c   = (2 * s + (lane >> 4)) ^ ((row >> 1) & 3);
                ldsm_x4(af[mt][0], af[mt][1], af[mt][2], af[mt][3],
                        ab + (unsigned)((row * 4 + c) << 4));
            }
#pragma unroll
            for (int p = 0; p < 4; p++) {
                const int row = warpN * 64 + 16 * p + b_rowl;
                const int c   = (2 * s + b_hi) ^ ((row >> 1) & 3);
                unsigned int r0, r1, r2, r3;
                ldsm_x4(r0, r1, r2, r3, bb + (unsigned)((row * 4 + c) << 4));
                mma_f16(acc[0][2 * p],     af[0], r0, r1);
                mma_f16(acc[1][2 * p],     af[1], r0, r1);
                mma_f16(acc[0][2 * p + 1], af[0], r2, r3);
                mma_f16(acc[1][2 * p + 1], af[1], r2, r3);
            }
        }
    }

    // epilogue
    const int fr = lane >> 2;
    const int fc = lane & 3;
    const bool is64 = (mode == 2) && (pos[1] == 0);
    float* fout = (float*)out_v;
    __half* hout = (__half*)out_v;
#pragma unroll
    for (int mt = 0; mt < 2; mt++) {
        const int gr0 = bm + warpM * 32 + mt * 16 + fr;
#pragma unroll
        for (int nt = 0; nt < 8; nt++) {
            const int gc = bn + warpN * 64 + nt * 8 + 2 * fc;
            float4 v = acc[mt][nt];
#pragma unroll
            for (int half_ = 0; half_ < 2; half_++) {
                const int grow = gr0 + half_ * 8;
                float e = half_ ? v.z : v.x;
                float o = half_ ? v.w : v.y;
                if (mode == 0) {
                    *(float2*)(fout + (size_t)grow * DM + gc) = make_float2(e, o);
                } else {
                    const int si = grow & (SEQ - 1), bi = grow >> 11;
                    const int head = gc >> 7, dd = gc & (DH - 1);
                    if (mode == 2) {
                        const int p = dd >> 1;
                        const int posv_i = is64 ? pos[2 * si] : pos[si];
                        const float inv_freq =
                            exp2f(-(float)p * (13.287712379549449f / 64.0f));
                        const float ang = (float)posv_i * inv_freq;
                        float sn, cs;
                        sincosf(ang, &sn, &cs);
                        const float e2 = e * cs - o * sn;
                        const float o2 = o * cs + e * sn;
                        e = e2; o = o2;
                    }
                    __half* dst = hout + ((((size_t)bi * NH + head) * SEQ + si) * DH + dd);
                    *(__half2*)dst = __floats2half2_rn(e, o);
                }
            }
        }
    }
}

// ---------------------------------------------------------------------------
// FP16 causal flash attention (Br=128, Bc=64, d=128, 8 warps).
// S=QK^T via ldmatrix + mma.m16n8k16. PV keeps P ENTIRELY IN REGISTERS:
// the S-accumulator C-fragment layout equals the PV A-fragment layout, so
// P is packed to half2 in registers (no smem staging, no syncwarp).
// Strides (16B chunks): Q/K/V 17 -> conflict-free LDSM. Smem 69,632 B.
// ---------------------------------------------------------------------------
#define FQ_ST 17
#define FL_Q_CH (128 * FQ_ST)
#define FL_K_CH (64 * FQ_ST)
#define FL_V_CH (64 * FQ_ST)
#define FL_BYTES ((FL_Q_CH + FL_K_CH + FL_V_CH) * 16)   // 69,632

__global__ __launch_bounds__(256, 2)
void flash_f16_kernel(const __half* __restrict__ Q, const __half* __restrict__ K,
                      const __half* __restrict__ V, __half* __restrict__ Y)
{
    extern __shared__ __align__(16) __half smh[];
    __half* Qs = smh;
    __half* Ks = Qs + FL_Q_CH * 8;
    __half* Vs = Ks + FL_K_CH * 8;

    const int qb = (gridDim.x - 1) - blockIdx.x;  // heavy tiles first
    const int bh = blockIdx.y;
    const int b  = bh >> 4, h = bh & 15;
    const int tid  = threadIdx.x;
    const int warp = tid >> 5;
    const int lane = tid & 31;
    const int fr = lane >> 2;
    const int fc = lane & 3;

    const __half* Qb = Q + (size_t)bh * SEQ * DH;
    const __half* Kb = K + (size_t)bh * SEQ * DH;
    const __half* Vb = V + (size_t)bh * SEQ * DH;

    for (int i = tid; i < 128 * 16; i += 256) {
        const int r = i >> 4, c = i & 15;
        *(uint4*)&Qs[(r * FQ_ST + c) << 3] =
            *(const uint4*)&Qb[(size_t)(qb * 128 + r) * DH + 8 * c];
    }

    float4 oacc[16];
#pragma unroll
    for (int nt = 0; nt < 16; nt++) oacc[nt] = make_float4(0.f, 0.f, 0.f, 0.f);
    float m0 = -1e30f, m1 = -1e30f, l0 = 0.f, l1 = 0.f;
    const float scale = 0.08838834764831845f;

    const int r0g = qb * 128 + 16 * warp + fr;
    const int r1g = r0g + 8;

    const int a_rowl = lane & 15;
    const unsigned int q_base = smem_u32(Qs) +
        (unsigned)((((16 * warp + a_rowl) * FQ_ST) + (lane >> 4)) << 4);
    const int b_rowl = ((lane >> 4) << 3) + (lane & 7);
    const int b_hi   = (lane >> 3) & 1;
    unsigned int k_base[4];
#pragma unroll
    for (int p = 0; p < 4; p++)
        k_base[p] = smem_u32(Ks) +
            (unsigned)((((16 * p + b_rowl) * FQ_ST) + b_hi) << 4);
    const unsigned int v_base = smem_u32(Vs) +
        (unsigned)(((a_rowl * FQ_ST) + (lane >> 4)) << 4);

    const int nj = 2 * qb + 2;
    for (int jb = 0; jb < nj; jb++) {
        __syncthreads();
        for (int i = tid; i < 64 * 16; i += 256) {
            const int r = i >> 4, c = i & 15;
            *(uint4*)&Ks[(r * FQ_ST + c) << 3] =
                *(const uint4*)&Kb[(size_t)(jb * 64 + r) * DH + 8 * c];
            *(uint4*)&Vs[(r * FQ_ST + c) << 3] =
                *(const uint4*)&Vb[(size_t)(jb * 64 + r) * DH + 8 * c];
        }
        __syncthreads();

        // ---- S = Q K^T  (warp tile 16 x 64), 8 k16 steps ----
        float4 sacc[8];
#pragma unroll
        for (int nt = 0; nt < 8; nt++) sacc[nt] = make_float4(0.f, 0.f, 0.f, 0.f);

#pragma unroll 4
        for (int ks = 0; ks < 8; ks++) {
            unsigned int af[4];
            ldsm_x4(af[0], af[1], af[2], af[3], q_base + 32u * ks);
#pragma unroll
            for (int p = 0; p < 4; p++) {
                unsigned int r0, r1, r2, r3;
                ldsm_x4(r0, r1, r2, r3, k_base[p] + 32u * ks);
                mma_f16(sacc[2 * p],     af, r0, r1);
                mma_f16(sacc[2 * p + 1], af, r2, r3);
            }
        }

        // ---- scale + causal mask ----
        const bool domask = (jb * 64 + 63) > (qb * 128 + 16 * warp);
#pragma unroll
        for (int nt = 0; nt < 8; nt++) {
            const int c0 = jb * 64 + 8 * nt + 2 * fc;
            const int c1 = c0 + 1;
            sacc[nt].x *= scale; sacc[nt].y *= scale;
            sacc[nt].z *= scale; sacc[nt].w *= scale;
            if (domask) {
                if (c0 > r0g) sacc[nt].x = -1e30f;
                if (c1 > r0g) sacc[nt].y = -1e30f;
                if (c0 > r1g) sacc[nt].z = -1e30f;
                if (c1 > r1g) sacc[nt].w = -1e30f;
            }
        }

        // ---- online softmax (rows fr, fr+8; quad reduction) ----
        float mx0 = -1e30f, mx1 = -1e30f;
#pragma unroll
        for (int nt = 0; nt < 8; nt++) {
            mx0 = fmaxf(mx0, fmaxf(sacc[nt].x, sacc[nt].y));
            mx1 = fmaxf(mx1, fmaxf(sacc[nt].z, sacc[nt].w));
        }
        mx0 = fmaxf(mx0, __shfl_xor_sync(0xffffffffu, mx0, 1));
        mx0 = fmaxf(mx0, __shfl_xor_sync(0xffffffffu, mx0, 2));
        mx1 = fmaxf(mx1, __shfl_xor_sync(0xffffffffu, mx1, 1));
        mx1 = fmaxf(mx1, __shfl_xor_sync(0xffffffffu, mx1, 2));

        const float mn0 = fmaxf(m0, mx0);
        const float mn1 = fmaxf(m1, mx1);
        const float alpha0 = __expf(m0 - mn0);
        const float alpha1 = __expf(m1 - mn1);
        m0 = mn0; m1 = mn1;

        float rs0 = 0.f, rs1 = 0.f;
#pragma unroll
        for (int nt = 0; nt < 8; nt++) {
            sacc[nt].x = __expf(sacc[nt].x - mn0);
            sacc[nt].y = __expf(sacc[nt].y - mn0);
            sacc[nt].z = __expf(sacc[nt].z - mn1);
            sacc[nt].w = __expf(sacc[nt].w - mn1);
            rs0 += sacc[nt].x + sacc[nt].y;
            rs1 += sacc[nt].z + sacc[nt].w;
        }
        rs0 += __shfl_xor_sync(0xffffffffu, rs0, 1);
        rs0 += __shfl_xor_sync(0xffffffffu, rs0, 2);
        rs1 += __shfl_xor_sync(0xffffffffu, rs1, 1);
        rs1 += __shfl_xor_sync(0xffffffffu, rs1, 2);
        l0 = l0 * alpha0 + rs0;
        l1 = l1 * alpha1 + rs1;

#pragma unroll
        for (int nt = 0; nt < 16; nt++) {
            oacc[nt].x *= alpha0; oacc[nt].y *= alpha0;
            oacc[nt].z *= alpha1; oacc[nt].w *= alpha1;
        }

        // ---- O += P V : P packed from sacc IN REGISTERS (no smem) ----
#pragma unroll
        for (int ks = 0; ks < 4; ks++) {
            unsigned int af[4];
            af[0] = pack_h2(sacc[2 * ks].x,     sacc[2 * ks].y);
            af[1] = pack_h2(sacc[2 * ks].z,     sacc[2 * ks].w);
            af[2] = pack_h2(sacc[2 * ks + 1].x, sacc[2 * ks + 1].y);
            af[3] = pack_h2(sacc[2 * ks + 1].z, sacc[2 * ks + 1].w);
#pragma unroll
            for (int nc2 = 0; nc2 < 8; nc2++) {
                unsigned int r0, r1, r2, r3;
                ldsm_x4_trans(r0, r1, r2, r3,
                              v_base + (unsigned)(ks * 16 * FQ_ST * 16) + 32u * nc2);
                mma_f16(oacc[2 * nc2],     af, r0, r1);
                mma_f16(oacc[2 * nc2 + 1], af, r2, r3);
            }
        }
    }

    // ---- epilogue: normalize, write half Y [b, s, h*128+d] ----
    const float inv0 = 1.0f / l0;
    const float inv1 = 1.0f / l1;
    const size_t y0 = ((size_t)(b * SEQ + r0g)) * DM + h * DH;
    const size_t y1 = ((size_t)(b * SEQ + r1g)) * DM + h * DH;
#pragma unroll
    for (int nt = 0; nt < 16; nt++) {
        const int cb = 8 * nt + 2 * fc;
        *(__half2*)&Y[y0 + cb] = __floats2half2_rn(oacc[nt].x * inv0, oacc[nt].y * inv0);
        *(__half2*)&Y[y1 + cb] = __floats2half2_rn(oacc[nt].z * inv1, oacc[nt].w * inv1);
    }
}

// ---------------------------------------------------------------------------
extern "C" void kernel_launch(void* const* d_in, const int* in_sizes, int n_in,
                              void* d_out, int out_size)
{
    (void)in_sizes; (void)n_in; (void)out_size;
    const float* x   = (const float*)d_in[0];
    const int*   pos = (const int*)d_in[1];   // int32 or int64: detected in-kernel
    const float* Wq  = (const float*)d_in[2];
    const float* Wk  = (const float*)d_in[3];
    const float* Wv  = (const float*)d_in[4];
    const float* Wo  = (const float*)d_in[5];
    float* out = (float*)d_out;

    __half *Qp, *Kp, *Vp, *Yp, *xh, *wqh, *wkh, *wvh, *woh;
    cudaGetSymbolAddress((void**)&Qp, g_Q);
    cudaGetSymbolAddress((void**)&Kp, g_K);
    cudaGetSymbolAddress((void**)&Vp, g_V);
    cudaGetSymbolAddress((void**)&Yp, g_Y);
    cudaGetSymbolAddress((void**)&xh, g_xh);
    cudaGetSymbolAddress((void**)&wqh, g_Wqh);
    cudaGetSymbolAddress((void**)&wkh, g_Wkh);
    cudaGetSymbolAddress((void**)&wvh, g_Wvh);
    cudaGetSymbolAddress((void**)&woh, g_Woh);

    // one-time fp16 conversion of x and weights
    const int xn4 = M_TOTAL * DM / 4;
    const int wn4 = DM * DM / 4;
    f2h_kernel<<<2048, 256>>>(x,  xh,  xn4);
    f2h_kernel<<<1024, 256>>>(Wq, wqh, wn4);
    f2h_kernel<<<1024, 256>>>(Wk, wkh, wn4);
    f2h_kernel<<<1024, 256>>>(Wv, wvh, wn4);
    f2h_kernel<<<1024, 256>>>(Wo, woh, wn4);

    cudaFuncSetAttribute(gemm_f16_cp,
                         cudaFuncAttributeMaxDynamicSharedMemorySize, GS_TOTAL);
    dim3 ggrid(DM / 128, M_TOTAL / 128);   // (16, 64)
    gemm_f16_cp<<<ggrid, 256, GS_TOTAL>>>(xh, wqh, Qp, 2, pos);  // + fused RoPE
    gemm_f16_cp<<<ggrid, 256, GS_TOTAL>>>(xh, wkh, Kp, 2, pos);  // + fused RoPE
    gemm_f16_cp<<<ggrid, 256, GS_TOTAL>>>(xh, wvh, Vp, 1, pos);

    cudaFuncSetAttribute(flash_f16_kernel,
                         cudaFuncAttributeMaxDynamicSharedMemorySize, FL_BYTES);
    flash_f16_kernel<<<dim3(SEQ / 128, BHEADS), 256, FL_BYTES>>>(Qp, Kp, Vp, Yp);

    gemm_f16_cp<<<ggrid, 256, GS_TOTAL>>>(Yp, woh, out, 0, pos);
}